// round 13
// baseline (speedup 1.0000x reference)
#include <cuda_runtime.h>
#include <cuda_bf16.h>
#include <math.h>
#include <stdint.h>

// Problem constants
#define BB   4
#define SS   2048
#define HID  1024
#define NH   16
#define HD   64
#define MR   (BB*SS)   // 8192 rows

// Pre-split bf16 operands for attention, layout [b][h][s][64]
__device__ __nv_bfloat16 g_qh[(size_t)MR * HID];
__device__ __nv_bfloat16 g_ql[(size_t)MR * HID];
__device__ __nv_bfloat16 g_kh[(size_t)MR * HID];
__device__ __nv_bfloat16 g_kl[(size_t)MR * HID];
__device__ __nv_bfloat16 g_vh[(size_t)MR * HID];
__device__ __nv_bfloat16 g_vl[(size_t)MR * HID];
// Pre-split GEMM operands
__device__ __nv_bfloat16 g_xh [(size_t)MR * HID];
__device__ __nv_bfloat16 g_xl [(size_t)MR * HID];
__device__ __nv_bfloat16 g_aoh[(size_t)MR * HID];
__device__ __nv_bfloat16 g_aol[(size_t)MR * HID];
__device__ __nv_bfloat16 g_wh [(size_t)3 * HID * HID];   // concat(q_w, kv_w)
__device__ __nv_bfloat16 g_wl [(size_t)3 * HID * HID];
__device__ __nv_bfloat16 g_owh[(size_t)HID * HID];
__device__ __nv_bfloat16 g_owl[(size_t)HID * HID];

__device__ __forceinline__ uint32_t smem_u32(const void* p) {
    uint32_t a;
    asm("{ .reg .u64 t; cvta.to.shared.u64 t, %1; cvt.u32.u64 %0, t; }"
        : "=r"(a) : "l"(p));
    return a;
}

__device__ __forceinline__ void bf16_split2(float x, float y,
                                            uint32_t& hi, uint32_t& lo) {
    __nv_bfloat16 hx = __float2bfloat16(x);
    __nv_bfloat16 hy = __float2bfloat16(y);
    __nv_bfloat16 lx = __float2bfloat16(x - __bfloat162float(hx));
    __nv_bfloat16 ly = __float2bfloat16(y - __bfloat162float(hy));
    __nv_bfloat162 h; h.x = hx; h.y = hy;
    __nv_bfloat162 l; l.x = lx; l.y = ly;
    hi = *reinterpret_cast<uint32_t*>(&h);
    lo = *reinterpret_cast<uint32_t*>(&l);
}

#define LDM_X4(r0, r1, r2, r3, addr) \
    asm volatile("ldmatrix.sync.aligned.m8n8.x4.shared.b16 {%0,%1,%2,%3}, [%4];" \
                 : "=r"(r0), "=r"(r1), "=r"(r2), "=r"(r3) : "r"(addr))
#define LDM_X4T(r0, r1, r2, r3, addr) \
    asm volatile("ldmatrix.sync.aligned.m8n8.x4.trans.shared.b16 {%0,%1,%2,%3}, [%4];" \
                 : "=r"(r0), "=r"(r1), "=r"(r2), "=r"(r3) : "r"(addr))

#define MMA_BF16(d, a, b0v, b1v) \
    asm volatile("mma.sync.aligned.m16n8k16.row.col.f32.bf16.bf16.f32 " \
                 "{%0,%1,%2,%3}, {%4,%5,%6,%7}, {%8,%9}, {%0,%1,%2,%3};" \
                 : "+f"((d)[0]), "+f"((d)[1]), "+f"((d)[2]), "+f"((d)[3]) \
                 : "r"((a)[0]), "r"((a)[1]), "r"((a)[2]), "r"((a)[3]), \
                   "r"(b0v), "r"(b1v))

#define CP_ASYNC16(dst, src) \
    asm volatile("cp.async.cg.shared.global [%0], [%1], 16;" \
                 :: "r"(dst), "l"(src) : "memory")
#define CP_COMMIT() asm volatile("cp.async.commit_group;" ::: "memory")
#define CP_WAIT1()  asm volatile("cp.async.wait_group 1;" ::: "memory")
#define CP_WAIT0()  asm volatile("cp.async.wait_group 0;" ::: "memory")

// ============================================================================
// Merged split: fp32 -> bf16 hi/lo for x, q_w, kv_w, out_w in ONE launch
// ============================================================================
#define NX4   (MR * HID / 4)
#define NQW4  (HID * HID / 4)
#define NKVW4 (2 * HID * HID / 4)
#define NOW4  (HID * HID / 4)
#define NSPLIT4 (NX4 + NQW4 + NKVW4 + NOW4)

__global__ __launch_bounds__(256)
void split_all(const float* __restrict__ x, const float* __restrict__ qw,
               const float* __restrict__ kvw, const float* __restrict__ ow)
{
    int i = blockIdx.x * blockDim.x + threadIdx.x;
    if (i >= NSPLIT4) return;
    const float* src;
    __nv_bfloat16 *dh, *dl;
    int off;
    if (i < NX4) {
        src = x; dh = g_xh; dl = g_xl; off = i;
    } else if (i < NX4 + NQW4) {
        src = qw; dh = g_wh; dl = g_wl; off = i - NX4;
    } else if (i < NX4 + NQW4 + NKVW4) {
        src = kvw; off = i - NX4 - NQW4;
        dh = g_wh + (size_t)HID * HID; dl = g_wl + (size_t)HID * HID;
    } else {
        src = ow; dh = g_owh; dl = g_owl; off = i - NX4 - NQW4 - NKVW4;
    }
    float4 v = *reinterpret_cast<const float4*>(src + (size_t)off * 4);
    uint32_t h0, l0, h1, l1;
    bf16_split2(v.x, v.y, h0, l0);
    bf16_split2(v.z, v.w, h1, l1);
    *reinterpret_cast<uint2*>(dh + (size_t)off * 4) = make_uint2(h0, h1);
    *reinterpret_cast<uint2*>(dl + (size_t)off * 4) = make_uint2(l0, l1);
}

// ============================================================================
// GEMM: CTA tile 256m x 128n, 8 warps (64x64 warp tiles), 1 CTA/SM.
// B fragments amortized over 2x M -> smem-read cyc < tensor cyc (tensor-bound).
// Dynamic smem: 2 stages x (Ah|Al 256x40 + Bh|Bl 128x40) bf16 = 122880 B.
// ============================================================================
#define KC    32
#define PITCH 40
#define A_EL  (256 * PITCH)
#define B_EL  (128 * PITCH)
#define STAGE_EL (2 * A_EL + 2 * B_EL)      // 30720 elements
#define GEMM_SMEM (2 * STAGE_EL * 2)        // 122880 bytes

// issue one stage with 256 threads: A arrays 1024 chunks, B arrays 512 chunks
#define GEMM_ISSUE_DEF                                                            \
    auto issue = [&](int s, int bsel) {                                           \
        const int k0 = s * KC;                                                    \
        uint32_t base = sb_u + (uint32_t)bsel * STAGE_EL * 2u;                    \
        _Pragma("unroll")                                                         \
        for (int a = 0; a < 2; a++) {                                             \
            _Pragma("unroll")                                                     \
            for (int t = 0; t < 4; t++) {                                         \
                int idx = tid + t * 256;        /* 0..1023 */                     \
                int r   = idx >> 2;                                               \
                int c   = (idx & 3) * 8;                                          \
                uint32_t dst = base + (uint32_t)(a * A_EL + r * PITCH + c) * 2u;  \
                CP_ASYNC16(dst, srcA[a] + (size_t)r * K + k0 + c);                \
            }                                                                     \
        }                                                                         \
        _Pragma("unroll")                                                         \
        for (int a = 0; a < 2; a++) {                                             \
            _Pragma("unroll")                                                     \
            for (int t = 0; t < 2; t++) {                                         \
                int idx = tid + t * 256;        /* 0..511 */                      \
                int r   = idx >> 2;                                               \
                int c   = (idx & 3) * 8;                                          \
                uint32_t dst = base + (uint32_t)(2 * A_EL + a * B_EL + r * PITCH + c) * 2u; \
                CP_ASYNC16(dst, srcB[a] + (size_t)r * K + k0 + c);                \
            }                                                                     \
        }                                                                         \
        CP_COMMIT();                                                              \
    };

// R10-order mainloop (load all frags, then 3 term-major passes)
#define GEMM_MAINLOOP64(acc)                                                      \
    for (int s = 0; s < NS; s++) {                                                \
        if (s < NS - 1) { CP_WAIT1(); } else { CP_WAIT0(); }                      \
        __syncthreads();                                                          \
        const uint32_t stg = sb_u + (uint32_t)((s & 1) * STAGE_EL) * 2u;          \
        const uint32_t bAh = stg;                                                 \
        const uint32_t bAl = stg + (uint32_t)A_EL * 2u;                           \
        const uint32_t bBh = stg + (uint32_t)(2 * A_EL) * 2u;                     \
        const uint32_t bBl = stg + (uint32_t)(2 * A_EL + B_EL) * 2u;              \
        _Pragma("unroll")                                                         \
        for (int kk = 0; kk < KC; kk += 16) {                                     \
            uint32_t bh[16], bl[16];                                              \
            _Pragma("unroll")                                                     \
            for (int p = 0; p < 4; p++) {                                         \
                uint32_t off = (uint32_t)((wn + p * 16 + b_n) * PITCH + kk + b_k) * 2u; \
                LDM_X4(bh[p*4+0], bh[p*4+1], bh[p*4+2], bh[p*4+3], bBh + off);    \
                LDM_X4(bl[p*4+0], bl[p*4+1], bl[p*4+2], bl[p*4+3], bBl + off);    \
            }                                                                     \
            uint32_t ah[4][4], al[4][4];                                          \
            _Pragma("unroll")                                                     \
            for (int mt = 0; mt < 4; mt++) {                                      \
                uint32_t off = (uint32_t)((wm + mt * 16 + a_row) * PITCH + kk + a_k) * 2u; \
                LDM_X4(ah[mt][0], ah[mt][1], ah[mt][2], ah[mt][3], bAh + off);    \
                LDM_X4(al[mt][0], al[mt][1], al[mt][2], al[mt][3], bAl + off);    \
            }                                                                     \
            _Pragma("unroll")                                                     \
            for (int mt = 0; mt < 4; mt++)                                        \
                _Pragma("unroll")                                                 \
                for (int nt = 0; nt < 8; nt++) {                                  \
                    int p = nt >> 1, o = (nt & 1) * 2;                            \
                    MMA_BF16(acc[mt][nt], ah[mt], bh[p*4+o], bh[p*4+o+1]);        \
                }                                                                 \
            _Pragma("unroll")                                                     \
            for (int mt = 0; mt < 4; mt++)                                        \
                _Pragma("unroll")                                                 \
                for (int nt = 0; nt < 8; nt++) {                                  \
                    int p = nt >> 1, o = (nt & 1) * 2;                            \
                    MMA_BF16(acc[mt][nt], ah[mt], bl[p*4+o], bl[p*4+o+1]);        \
                }                                                                 \
            _Pragma("unroll")                                                     \
            for (int mt = 0; mt < 4; mt++)                                        \
                _Pragma("unroll")                                                 \
                for (int nt = 0; nt < 8; nt++) {                                  \
                    int p = nt >> 1, o = (nt & 1) * 2;                            \
                    MMA_BF16(acc[mt][nt], al[mt], bh[p*4+o], bh[p*4+o+1]);        \
                }                                                                 \
        }                                                                         \
        __syncthreads();                                                          \
        if (s + 2 < NS) issue(s + 2, s & 1);                                      \
    }

// ============================================================================
// Merged QKV GEMM + fused qknorm/split/relayout epilogue (256x128 CTA tile).
// Warp layout: 4 m-rows x 2 n-cols; each warp owns one full 64-dim head.
// ============================================================================
__global__ __launch_bounds__(256, 1)
void gemm_qkv(const __nv_bfloat16* __restrict__ Ah, const __nv_bfloat16* __restrict__ Al,
              const __nv_bfloat16* __restrict__ Wh, const __nv_bfloat16* __restrict__ Wl,
              const float* __restrict__ q_b, const float* __restrict__ kv_b,
              const float* __restrict__ gq, const float* __restrict__ gk)
{
    extern __shared__ __nv_bfloat16 sbuf[];

    const int K = HID;
    const int tid  = threadIdx.x;
    const int wid  = tid >> 5;
    const int lane = tid & 31;
    const int row0 = blockIdx.y * 256;
    const int col0 = blockIdx.x * 128;
    const int wm   = (wid >> 1) * 64;
    const int wn   = (wid & 1) * 64;

    const uint32_t sb_u = smem_u32(sbuf);
    const __nv_bfloat16* srcA[2] = { Ah + (size_t)row0 * K, Al + (size_t)row0 * K };
    const __nv_bfloat16* srcB[2] = { Wh + (size_t)col0 * K, Wl + (size_t)col0 * K };

    const int NS = K / KC;
    GEMM_ISSUE_DEF

    issue(0, 0);
    issue(1, 1);

    const int a_row = lane & 15;
    const int a_k   = (lane >> 4) << 3;
    const int b_n   = (lane & 7) + ((lane >> 4) << 3);
    const int b_k   = lane & 8;

    float acc[4][8][4];
#pragma unroll
    for (int mt = 0; mt < 4; mt++)
#pragma unroll
        for (int nt = 0; nt < 8; nt++)
#pragma unroll
            for (int r = 0; r < 4; r++) acc[mt][nt][r] = 0.f;

    GEMM_MAINLOOP64(acc)

    // ---- fused epilogue (one head per warp-column) ----
    const int g  = lane >> 2;
    const int t2 = (lane & 3) * 2;

#pragma unroll
    for (int nt = 0; nt < 8; nt++) {
        int col = col0 + wn + nt * 8 + t2;
        float b0 = (col < HID) ? __ldg(&q_b[col])     : __ldg(&kv_b[col - HID]);
        float b1 = (col + 1 < HID) ? __ldg(&q_b[col + 1]) : __ldg(&kv_b[col + 1 - HID]);
#pragma unroll
        for (int mt = 0; mt < 4; mt++) {
            acc[mt][nt][0] += b0; acc[mt][nt][1] += b1;
            acc[mt][nt][2] += b0; acc[mt][nt][3] += b1;
        }
    }

    const int seg = (col0 < HID) ? 0 : (col0 < 2 * HID) ? 1 : 2;
    const int h   = ((col0 & (HID - 1)) + wn) >> 6;
    __nv_bfloat16* dh = (seg == 0) ? g_qh : (seg == 1) ? g_kh : g_vh;
    __nv_bfloat16* dl = (seg == 0) ? g_ql : (seg == 1) ? g_kl : g_vl;
    const float* gamma = (seg == 0) ? gq : gk;

#pragma unroll
    for (int mt = 0; mt < 4; mt++) {
#pragma unroll
        for (int rh = 0; rh < 2; rh++) {
            float inv = 1.0f;
            if (seg < 2) {
                float ssum = 0.f;
#pragma unroll
                for (int nt = 0; nt < 8; nt++) {
                    float v0 = acc[mt][nt][rh * 2 + 0];
                    float v1 = acc[mt][nt][rh * 2 + 1];
                    ssum += v0 * v0 + v1 * v1;
                }
                ssum += __shfl_xor_sync(0xffffffffu, ssum, 1);
                ssum += __shfl_xor_sync(0xffffffffu, ssum, 2);
                inv = 8.0f / fmaxf(sqrtf(ssum), 1e-12f);
            }
            int row  = row0 + wm + mt * 16 + g + rh * 8;
            int b    = row >> 11;
            int srow = row & (SS - 1);
            size_t base = ((size_t)(b * NH + h) * SS + srow) * HD;
#pragma unroll
            for (int nt = 0; nt < 8; nt++) {
                int d = nt * 8 + t2;
                float g0 = 1.f, g1 = 1.f;
                if (seg < 2) {
                    g0 = __ldg(&gamma[h * HD + d]);
                    g1 = __ldg(&gamma[h * HD + d + 1]);
                }
                float v0 = acc[mt][nt][rh * 2 + 0] * inv * g0;
                float v1 = acc[mt][nt][rh * 2 + 1] * inv * g1;
                uint32_t hi, lo;
                bf16_split2(v0, v1, hi, lo);
                *reinterpret_cast<uint32_t*>(&dh[base + d]) = hi;
                *reinterpret_cast<uint32_t*>(&dl[base + d]) = lo;
            }
        }
    }
}

// ============================================================================
// Out-proj GEMM (fp32 out), 256x128 CTA tile, 8 warps.
// ============================================================================
__global__ __launch_bounds__(256, 1)
void gemm_pre(const __nv_bfloat16* __restrict__ Ah, const __nv_bfloat16* __restrict__ Al,
              const __nv_bfloat16* __restrict__ Wh, const __nv_bfloat16* __restrict__ Wl,
              float* __restrict__ C, int M, int N, int K)
{
    extern __shared__ __nv_bfloat16 sbuf[];

    const int tid  = threadIdx.x;
    const int wid  = tid >> 5;
    const int lane = tid & 31;
    const int row0 = blockIdx.y * 256;
    const int col0 = blockIdx.x * 128;
    const int wm   = (wid >> 1) * 64;
    const int wn   = (wid & 1) * 64;

    const uint32_t sb_u = smem_u32(sbuf);
    const __nv_bfloat16* srcA[2] = { Ah + (size_t)row0 * K, Al + (size_t)row0 * K };
    const __nv_bfloat16* srcB[2] = { Wh + (size_t)col0 * K, Wl + (size_t)col0 * K };

    const int NS = K / KC;
    GEMM_ISSUE_DEF

    issue(0, 0);
    issue(1, 1);

    const int a_row = lane & 15;
    const int a_k   = (lane >> 4) << 3;
    const int b_n   = (lane & 7) + ((lane >> 4) << 3);
    const int b_k   = lane & 8;

    float acc[4][8][4];
#pragma unroll
    for (int mt = 0; mt < 4; mt++)
#pragma unroll
        for (int nt = 0; nt < 8; nt++)
#pragma unroll
            for (int r = 0; r < 4; r++) acc[mt][nt][r] = 0.f;

    GEMM_MAINLOOP64(acc)

    const int g  = lane >> 2;
    const int t2 = (lane & 3) * 2;
#pragma unroll
    for (int mt = 0; mt < 4; mt++) {
#pragma unroll
        for (int nt = 0; nt < 8; nt++) {
            int row = row0 + wm + mt * 16 + g;
            int col = col0 + wn + nt * 8 + t2;
            *reinterpret_cast<float2*>(&C[(size_t)row * N + col]) =
                make_float2(acc[mt][nt][0], acc[mt][nt][1]);
            *reinterpret_cast<float2*>(&C[(size_t)(row + 8) * N + col]) =
                make_float2(acc[mt][nt][2], acc[mt][nt][3]);
        }
    }
}

// ============================================================================
// Tensor-core flash attention: 4 warps x 32 query rows (round-10 proven).
// ============================================================================
#define APITCH 72
#define QTILE_EL  (128 * APITCH)
#define KVARR_EL  (64 * APITCH)
#define BUF_EL    (4 * KVARR_EL)
#define ATT_SMEM  ((2 * QTILE_EL + 2 * BUF_EL) * 2)   // 110592 bytes
#define NT        (SS / 64)

__global__ __launch_bounds__(128, 2)
void attn_mma(const __nv_bfloat16* __restrict__ qh, const __nv_bfloat16* __restrict__ ql,
              const __nv_bfloat16* __restrict__ kh, const __nv_bfloat16* __restrict__ kl,
              const __nv_bfloat16* __restrict__ vh, const __nv_bfloat16* __restrict__ vl,
              __nv_bfloat16* __restrict__ aoh, __nv_bfloat16* __restrict__ aol)
{
    extern __shared__ __nv_bfloat16 sm[];
    __nv_bfloat16* Qh = sm;
    __nv_bfloat16* Ql = Qh + QTILE_EL;
    __nv_bfloat16* Bf = Ql + QTILE_EL;

    const int tid  = threadIdx.x;
    const int wid  = tid >> 5;
    const int lane = tid & 31;
    const int bh   = blockIdx.y;
    const int q0   = blockIdx.x * 128;
    const int wm   = wid * 32;
    const size_t bh_off = (size_t)bh * SS * HD;

    const __nv_bfloat16* srcs[4] = {kh + bh_off, kl + bh_off, vh + bh_off, vl + bh_off};
    const uint32_t buf_u[2] = { smem_u32(Bf), smem_u32(Bf + BUF_EL) };
    const uint32_t Qh_u = smem_u32(Qh);
    const uint32_t Ql_u = smem_u32(Ql);

    auto issue = [&](int kt, int bsel) {
#pragma unroll
        for (int i = 0; i < 16; i++) {
            const __nv_bfloat16* sp = srcs[i >> 2];
            int rem = ((i & 3) << 7) + tid;
            int r = rem >> 3;
            int c = (rem & 7) * 8;
            uint32_t dst = buf_u[bsel] + (uint32_t)((i >> 2) * KVARR_EL + r * APITCH + c) * 2u;
            CP_ASYNC16(dst, sp + (size_t)(kt * 64 + r) * HD + c);
        }
        CP_COMMIT();
    };

    issue(0, 0);
    issue(1, 1);

    {
        const __nv_bfloat16* qsrc[2] = {qh + bh_off, ql + bh_off};
        __nv_bfloat16* qdst[2] = {Qh, Ql};
#pragma unroll
        for (int i = 0; i < 16; i++) {
            int rem = ((i & 7) << 7) + tid;
            int r = rem >> 3;
            int c = (rem & 7) * 8;
            uint4 v = *reinterpret_cast<const uint4*>(
                qsrc[i >> 3] + (size_t)(q0 + r) * HD + c);
            *reinterpret_cast<uint4*>(qdst[i >> 3] + r * APITCH + c) = v;
        }
    }
    __syncthreads();

    const int a_row = lane & 15;
    const int a_k   = (lane >> 4) << 3;
    const int b_n   = (lane & 7) + ((lane >> 4) << 3);
    const int b_k   = lane & 8;

    float m_run[2][2], l_run[2][2];
    float O[2][8][4];
#pragma unroll
    for (int mt = 0; mt < 2; mt++) {
        m_run[mt][0] = -1e30f; m_run[mt][1] = -1e30f;
        l_run[mt][0] = 0.f;    l_run[mt][1] = 0.f;
#pragma unroll
        for (int d = 0; d < 8; d++)
#pragma unroll
            for (int r = 0; r < 4; r++) O[mt][d][r] = 0.f;
    }

    for (int t = 0; t < NT; t++) {
        if (t < NT - 1) { CP_WAIT1(); } else { CP_WAIT0(); }
        __syncthreads();

        const uint32_t Ks_h = buf_u[t & 1];
        const uint32_t Ks_l = Ks_h + KVARR_EL * 2u;
        const uint32_t Vs_h = Ks_h + 2u * KVARR_EL * 2u;
        const uint32_t Vs_l = Ks_h + 3u * KVARR_EL * 2u;

        float S[2][8][4];
#pragma unroll
        for (int mt = 0; mt < 2; mt++)
#pragma unroll
            for (int nt = 0; nt < 8; nt++)
#pragma unroll
                for (int r = 0; r < 4; r++) S[mt][nt][r] = 0.f;

#pragma unroll
        for (int ks = 0; ks < 4; ks++) {
            uint32_t kfh[4][4], kfl[4][4];
#pragma unroll
            for (int p = 0; p < 4; p++) {
                uint32_t off = (uint32_t)((p * 16 + b_n) * APITCH + ks * 16 + b_k) * 2u;
                LDM_X4(kfh[p][0], kfh[p][1], kfh[p][2], kfh[p][3], Ks_h + off);
                LDM_X4(kfl[p][0], kfl[p][1], kfl[p][2], kfl[p][3], Ks_l + off);
            }
            uint32_t qfh[2][4], qfl[2][4];
#pragma unroll
            for (int mt = 0; mt < 2; mt++) {
                uint32_t off = (uint32_t)((wm + mt * 16 + a_row) * APITCH + ks * 16 + a_k) * 2u;
                LDM_X4(qfh[mt][0], qfh[mt][1], qfh[mt][2], qfh[mt][3], Qh_u + off);
                LDM_X4(qfl[mt][0], qfl[mt][1], qfl[mt][2], qfl[mt][3], Ql_u + off);
            }
#pragma unroll
            for (int mt = 0; mt < 2; mt++)
#pragma unroll
                for (int nt = 0; nt < 8; nt++) {
                    int p = nt >> 1, o = (nt & 1) * 2;
                    MMA_BF16(S[mt][nt], qfh[mt], kfh[p][o], kfh[p][o+1]);
                }
#pragma unroll
            for (int mt = 0; mt < 2; mt++)
#pragma unroll
                for (int nt = 0; nt < 8; nt++) {
                    int p = nt >> 1, o = (nt & 1) * 2;
                    MMA_BF16(S[mt][nt], qfh[mt], kfl[p][o], kfl[p][o+1]);
                }
#pragma unroll
            for (int mt = 0; mt < 2; mt++)
#pragma unroll
                for (int nt = 0; nt < 8; nt++) {
                    int p = nt >> 1, o = (nt & 1) * 2;
                    MMA_BF16(S[mt][nt], qfl[mt], kfh[p][o], kfh[p][o+1]);
                }
        }

#pragma unroll
        for (int mt = 0; mt < 2; mt++) {
            float mx0 = -1e30f, mx1 = -1e30f;
#pragma unroll
            for (int nt = 0; nt < 8; nt++) {
                mx0 = fmaxf(mx0, fmaxf(S[mt][nt][0], S[mt][nt][1]));
                mx1 = fmaxf(mx1, fmaxf(S[mt][nt][2], S[mt][nt][3]));
            }
            mx0 = fmaxf(mx0, __shfl_xor_sync(0xffffffffu, mx0, 1));
            mx0 = fmaxf(mx0, __shfl_xor_sync(0xffffffffu, mx0, 2));
            mx1 = fmaxf(mx1, __shfl_xor_sync(0xffffffffu, mx1, 1));
            mx1 = fmaxf(mx1, __shfl_xor_sync(0xffffffffu, mx1, 2));
            float mn0 = fmaxf(m_run[mt][0], mx0), mn1 = fmaxf(m_run[mt][1], mx1);
            float c0 = __expf(m_run[mt][0] - mn0), c1 = __expf(m_run[mt][1] - mn1);
            m_run[mt][0] = mn0; m_run[mt][1] = mn1;

            float s0 = 0.f, s1 = 0.f;
#pragma unroll
            for (int nt = 0; nt < 8; nt++) {
                S[mt][nt][0] = __expf(S[mt][nt][0] - mn0);
                S[mt][nt][1] = __expf(S[mt][nt][1] - mn0);
                S[mt][nt][2] = __expf(S[mt][nt][2] - mn1);
                S[mt][nt][3] = __expf(S[mt][nt][3] - mn1);
                s0 += S[mt][nt][0] + S[mt][nt][1];
                s1 += S[mt][nt][2] + S[mt][nt][3];
            }
            s0 += __shfl_xor_sync(0xffffffffu, s0, 1);
            s0 += __shfl_xor_sync(0xffffffffu, s0, 2);
            s1 += __shfl_xor_sync(0xffffffffu, s1, 1);
            s1 += __shfl_xor_sync(0xffffffffu, s1, 2);
            l_run[mt][0] = l_run[mt][0] * c0 + s0;
            l_run[mt][1] = l_run[mt][1] * c1 + s1;
#pragma unroll
            for (int d = 0; d < 8; d++) {
                O[mt][d][0] *= c0; O[mt][d][1] *= c0;
                O[mt][d][2] *= c1; O[mt][d][3] *= c1;
            }
        }

#pragma unroll
        for (int ks = 0; ks < 4; ks++) {
            uint32_t pfh[2][4], pfl[2][4];
#pragma unroll
            for (int mt = 0; mt < 2; mt++) {
                bf16_split2(S[mt][2*ks][0],   S[mt][2*ks][1],   pfh[mt][0], pfl[mt][0]);
                bf16_split2(S[mt][2*ks][2],   S[mt][2*ks][3],   pfh[mt][1], pfl[mt][1]);
                bf16_split2(S[mt][2*ks+1][0], S[mt][2*ks+1][1], pfh[mt][2], pfl[mt][2]);
                bf16_split2(S[mt][2*ks+1][2], S[mt][2*ks+1][3], pfh[mt][3], pfl[mt][3]);
            }
            uint32_t vfh[4][4], vfl[4][4];
#pragma unroll
            for (int pd = 0; pd < 4; pd++) {
                uint32_t off = (uint32_t)((ks * 16 + (lane & 15)) * APITCH +
                                          pd * 16 + ((lane >> 4) << 3)) * 2u;
                LDM_X4T(vfh[pd][0], vfh[pd][1], vfh[pd][2], vfh[pd][3], Vs_h + off);
                LDM_X4T(vfl[pd][0], vfl[pd][1], vfl[pd][2], vfl[pd][3], Vs_l + off);
            }
#pragma unroll
            for (int mt = 0; mt < 2; mt++)
#pragma unroll
                for (int dt = 0; dt < 8; dt++) {
                    int pd = dt >> 1, o = (dt & 1) * 2;
                    MMA_BF16(O[mt][dt], pfh[mt], vfh[pd][o], vfh[pd][o+1]);
                }
#pragma unroll
            for (int mt = 0; mt < 2; mt++)
#pragma unroll
                for (int dt = 0; dt < 8; dt++) {
                    int pd = dt >> 1, o = (dt & 1) * 2;
                    MMA_BF16(O[mt][dt], pfh[mt], vfl[pd][o], vfl[pd][o+1]);
                }
#pragma unroll
            for (int mt = 0; mt < 2; mt++)
#pragma unroll
                for (int dt = 0; dt < 8; dt++) {
                    int pd = dt >> 1, o = (dt & 1) * 2;
                    MMA_BF16(O[mt][dt], pfl[mt], vfh[pd][o], vfh[pd][o+1]);
                }
        }

        __syncthreads();
        if (t + 2 < NT) issue(t + 2, t & 1);
    }

    const int g  = lane >> 2;
    const int t2 = (lane & 3) * 2;
    const int b  = bh >> 4;
    const int h  = bh & 15;
#pragma unroll
    for (int mt = 0; mt < 2; mt++) {
        float inv0 = 1.0f / l_run[mt][0], inv1 = 1.0f / l_run[mt][1];
        int row = b * SS + q0 + wm + mt * 16 + g;
#pragma unroll
        for (int dt = 0; dt < 8; dt++) {
            int col = h * HD + dt * 8 + t2;
            uint32_t hi, lo;
            bf16_split2(O[mt][dt][0] * inv0, O[mt][dt][1] * inv0, hi, lo);
            *reinterpret_cast<uint32_t*>(&aoh[(size_t)row * HID + col]) = hi;
            *reinterpret_cast<uint32_t*>(&aol[(size_t)row * HID + col]) = lo;
            bf16_split2(O[mt][dt][2] * inv1, O[mt][dt][3] * inv1, hi, lo);
            *reinterpret_cast<uint32_t*>(&aoh[(size_t)(row + 8) * HID + col]) = hi;
            *reinterpret_cast<uint32_t*>(&aol[(size_t)(row + 8) * HID + col]) = lo;
        }
    }
}

// ----------------------------------------------------------------------------
// Launch
// ----------------------------------------------------------------------------
extern "C" void kernel_launch(void* const* d_in, const int* in_sizes, int n_in,
                              void* d_out, int out_size)
{
    const float* x     = (const float*)d_in[0];
    const float* q_w   = (const float*)d_in[1];
    const float* q_b   = (const float*)d_in[2];
    const float* kv_w  = (const float*)d_in[3];
    const float* kv_b  = (const float*)d_in[4];
    const float* gq    = (const float*)d_in[5];
    const float* gk    = (const float*)d_in[6];
    const float* out_w = (const float*)d_in[7];
    float* out = (float*)d_out;

    __nv_bfloat16 *pqh, *pql, *pkh, *pkl, *pvh, *pvl;
    cudaGetSymbolAddress((void**)&pqh, g_qh);
    cudaGetSymbolAddress((void**)&pql, g_ql);
    cudaGetSymbolAddress((void**)&pkh, g_kh);
    cudaGetSymbolAddress((void**)&pkl, g_kl);
    cudaGetSymbolAddress((void**)&pvh, g_vh);
    cudaGetSymbolAddress((void**)&pvl, g_vl);
    __nv_bfloat16 *pxh, *pxl, *paoh, *paol, *pwh, *pwl, *powh, *powl;
    cudaGetSymbolAddress((void**)&pxh,  g_xh);
    cudaGetSymbolAddress((void**)&pxl,  g_xl);
    cudaGetSymbolAddress((void**)&paoh, g_aoh);
    cudaGetSymbolAddress((void**)&paol, g_aol);
    cudaGetSymbolAddress((void**)&pwh,  g_wh);
    cudaGetSymbolAddress((void**)&pwl,  g_wl);
    cudaGetSymbolAddress((void**)&powh, g_owh);
    cudaGetSymbolAddress((void**)&powl, g_owl);

    cudaFuncSetAttribute(attn_mma,
                         cudaFuncAttributeMaxDynamicSharedMemorySize, ATT_SMEM);
    cudaFuncSetAttribute(gemm_qkv,
                         cudaFuncAttributeMaxDynamicSharedMemorySize, GEMM_SMEM);
    cudaFuncSetAttribute(gemm_pre,
                         cudaFuncAttributeMaxDynamicSharedMemorySize, GEMM_SMEM);

    // Pre-split inputs + all weights (one launch)
    split_all<<<(NSPLIT4 + 255) / 256, 256>>>(x, q_w, kv_w, out_w);

    // Merged QKV projection + fused qknorm/split/relayout (256x128 tile)
    {
        dim3 grid((3 * HID) / 128, MR / 256);   // (24, 32)
        gemm_qkv<<<grid, 256, GEMM_SMEM>>>(pxh, pxl, pwh, pwl, q_b, kv_b, gq, gk);
    }
    // Attention (tensor cores, 128 queries/CTA, 4 warps x 32 rows, 2 CTA/SM)
    {
        dim3 grid(SS / 128, BB * NH);           // (16, 64)
        attn_mma<<<grid, 128, ATT_SMEM>>>(pqh, pql, pkh, pkl, pvh, pvl, paoh, paol);
    }
    // Output projection (256x128 tile)
    {
        dim3 grid(HID / 128, MR / 256);         // (8, 32)
        gemm_pre<<<grid, 256, GEMM_SMEM>>>(paoh, paol, powh, powl, out, MR, HID, HID);
    }
}

// round 14
// speedup vs baseline: 1.0574x; 1.0574x over previous
#include <cuda_runtime.h>
#include <cuda_bf16.h>
#include <math.h>
#include <stdint.h>

// Problem constants
#define BB   4
#define SS   2048
#define HID  1024
#define NH   16
#define HD   64
#define MR   (BB*SS)   // 8192 rows

// Pre-split bf16 operands for attention, layout [b][h][s][64]
__device__ __nv_bfloat16 g_qh[(size_t)MR * HID];
__device__ __nv_bfloat16 g_ql[(size_t)MR * HID];
__device__ __nv_bfloat16 g_kh[(size_t)MR * HID];
__device__ __nv_bfloat16 g_kl[(size_t)MR * HID];
__device__ __nv_bfloat16 g_vh[(size_t)MR * HID];
__device__ __nv_bfloat16 g_vl[(size_t)MR * HID];
// Pre-split GEMM operands
__device__ __nv_bfloat16 g_xh [(size_t)MR * HID];
__device__ __nv_bfloat16 g_xl [(size_t)MR * HID];
__device__ __nv_bfloat16 g_aoh[(size_t)MR * HID];
__device__ __nv_bfloat16 g_aol[(size_t)MR * HID];
__device__ __nv_bfloat16 g_wh [(size_t)3 * HID * HID];   // concat(q_w, kv_w)
__device__ __nv_bfloat16 g_wl [(size_t)3 * HID * HID];
__device__ __nv_bfloat16 g_owh[(size_t)HID * HID];
__device__ __nv_bfloat16 g_owl[(size_t)HID * HID];

__device__ __forceinline__ uint32_t smem_u32(const void* p) {
    uint32_t a;
    asm("{ .reg .u64 t; cvta.to.shared.u64 t, %1; cvt.u32.u64 %0, t; }"
        : "=r"(a) : "l"(p));
    return a;
}

__device__ __forceinline__ void bf16_split2(float x, float y,
                                            uint32_t& hi, uint32_t& lo) {
    __nv_bfloat16 hx = __float2bfloat16(x);
    __nv_bfloat16 hy = __float2bfloat16(y);
    __nv_bfloat16 lx = __float2bfloat16(x - __bfloat162float(hx));
    __nv_bfloat16 ly = __float2bfloat16(y - __bfloat162float(hy));
    __nv_bfloat162 h; h.x = hx; h.y = hy;
    __nv_bfloat162 l; l.x = lx; l.y = ly;
    hi = *reinterpret_cast<uint32_t*>(&h);
    lo = *reinterpret_cast<uint32_t*>(&l);
}

#define LDM_X4(r0, r1, r2, r3, addr) \
    asm volatile("ldmatrix.sync.aligned.m8n8.x4.shared.b16 {%0,%1,%2,%3}, [%4];" \
                 : "=r"(r0), "=r"(r1), "=r"(r2), "=r"(r3) : "r"(addr))
#define LDM_X4T(r0, r1, r2, r3, addr) \
    asm volatile("ldmatrix.sync.aligned.m8n8.x4.trans.shared.b16 {%0,%1,%2,%3}, [%4];" \
                 : "=r"(r0), "=r"(r1), "=r"(r2), "=r"(r3) : "r"(addr))

#define MMA_BF16(d, a, b0v, b1v) \
    asm volatile("mma.sync.aligned.m16n8k16.row.col.f32.bf16.bf16.f32 " \
                 "{%0,%1,%2,%3}, {%4,%5,%6,%7}, {%8,%9}, {%0,%1,%2,%3};" \
                 : "+f"((d)[0]), "+f"((d)[1]), "+f"((d)[2]), "+f"((d)[3]) \
                 : "r"((a)[0]), "r"((a)[1]), "r"((a)[2]), "r"((a)[3]), \
                   "r"(b0v), "r"(b1v))

#define CP_ASYNC16(dst, src) \
    asm volatile("cp.async.cg.shared.global [%0], [%1], 16;" \
                 :: "r"(dst), "l"(src) : "memory")
#define CP_COMMIT() asm volatile("cp.async.commit_group;" ::: "memory")
#define CP_WAIT1()  asm volatile("cp.async.wait_group 1;" ::: "memory")
#define CP_WAIT0()  asm volatile("cp.async.wait_group 0;" ::: "memory")

// ============================================================================
// Merged split: fp32 -> bf16 hi/lo for x, q_w, kv_w, out_w in ONE launch
// ============================================================================
#define NX4   (MR * HID / 4)
#define NQW4  (HID * HID / 4)
#define NKVW4 (2 * HID * HID / 4)
#define NOW4  (HID * HID / 4)
#define NSPLIT4 (NX4 + NQW4 + NKVW4 + NOW4)

__global__ __launch_bounds__(256)
void split_all(const float* __restrict__ x, const float* __restrict__ qw,
               const float* __restrict__ kvw, const float* __restrict__ ow)
{
    int i = blockIdx.x * blockDim.x + threadIdx.x;
    if (i >= NSPLIT4) return;
    const float* src;
    __nv_bfloat16 *dh, *dl;
    int off;
    if (i < NX4) {
        src = x; dh = g_xh; dl = g_xl; off = i;
    } else if (i < NX4 + NQW4) {
        src = qw; dh = g_wh; dl = g_wl; off = i - NX4;
    } else if (i < NX4 + NQW4 + NKVW4) {
        src = kvw; off = i - NX4 - NQW4;
        dh = g_wh + (size_t)HID * HID; dl = g_wl + (size_t)HID * HID;
    } else {
        src = ow; dh = g_owh; dl = g_owl; off = i - NX4 - NQW4 - NKVW4;
    }
    float4 v = *reinterpret_cast<const float4*>(src + (size_t)off * 4);
    uint32_t h0, l0, h1, l1;
    bf16_split2(v.x, v.y, h0, l0);
    bf16_split2(v.z, v.w, h1, l1);
    *reinterpret_cast<uint2*>(dh + (size_t)off * 4) = make_uint2(h0, h1);
    *reinterpret_cast<uint2*>(dl + (size_t)off * 4) = make_uint2(l0, l1);
}

// ============================================================================
// Shared GEMM pieces: 4 warps/CTA, warp tile 64m x 64n, CTA tile 128x128,
// 2 CTA/SM (round-10 proven configuration).
// ============================================================================
#define KC    32
#define PITCH 40
#define GT_EL (128 * PITCH)
#define GSTAGE_EL (4 * GT_EL)

#define GEMM_MAINLOOP64(acc)                                                      \
    for (int s = 0; s < NS; s++) {                                                \
        if (s < NS - 1) { CP_WAIT1(); } else { CP_WAIT0(); }                      \
        __syncthreads();                                                          \
        const uint32_t bAh = sb_u + (uint32_t)((s & 1) * GSTAGE_EL) * 2u;         \
        const uint32_t bAl = bAh + (uint32_t)GT_EL * 2u;                          \
        const uint32_t bBh = bAh + (uint32_t)(2 * GT_EL) * 2u;                    \
        const uint32_t bBl = bAh + (uint32_t)(3 * GT_EL) * 2u;                    \
        _Pragma("unroll")                                                         \
        for (int kk = 0; kk < KC; kk += 16) {                                     \
            uint32_t bh[16], bl[16];                                              \
            _Pragma("unroll")                                                     \
            for (int p = 0; p < 4; p++) {                                         \
                uint32_t off = (uint32_t)((wn + p * 16 + b_n) * PITCH + kk + b_k) * 2u; \
                LDM_X4(bh[p*4+0], bh[p*4+1], bh[p*4+2], bh[p*4+3], bBh + off);    \
                LDM_X4(bl[p*4+0], bl[p*4+1], bl[p*4+2], bl[p*4+3], bBl + off);    \
            }                                                                     \
            uint32_t ah[4][4], al[4][4];                                          \
            _Pragma("unroll")                                                     \
            for (int mt = 0; mt < 4; mt++) {                                      \
                uint32_t off = (uint32_t)((wm + mt * 16 + a_row) * PITCH + kk + a_k) * 2u; \
                LDM_X4(ah[mt][0], ah[mt][1], ah[mt][2], ah[mt][3], bAh + off);    \
                LDM_X4(al[mt][0], al[mt][1], al[mt][2], al[mt][3], bAl + off);    \
            }                                                                     \
            _Pragma("unroll")                                                     \
            for (int mt = 0; mt < 4; mt++)                                        \
                _Pragma("unroll")                                                 \
                for (int nt = 0; nt < 8; nt++) {                                  \
                    int p = nt >> 1, o = (nt & 1) * 2;                            \
                    MMA_BF16(acc[mt][nt], ah[mt], bh[p*4+o], bh[p*4+o+1]);        \
                }                                                                 \
            _Pragma("unroll")                                                     \
            for (int mt = 0; mt < 4; mt++)                                        \
                _Pragma("unroll")                                                 \
                for (int nt = 0; nt < 8; nt++) {                                  \
                    int p = nt >> 1, o = (nt & 1) * 2;                            \
                    MMA_BF16(acc[mt][nt], ah[mt], bl[p*4+o], bl[p*4+o+1]);        \
                }                                                                 \
            _Pragma("unroll")                                                     \
            for (int mt = 0; mt < 4; mt++)                                        \
                _Pragma("unroll")                                                 \
                for (int nt = 0; nt < 8; nt++) {                                  \
                    int p = nt >> 1, o = (nt & 1) * 2;                            \
                    MMA_BF16(acc[mt][nt], al[mt], bh[p*4+o], bh[p*4+o+1]);        \
                }                                                                 \
        }                                                                         \
        __syncthreads();                                                          \
        if (s + 2 < NS) issue(s + 2, s & 1);                                      \
    }

#define GEMM_ISSUE_DEF                                                            \
    auto issue = [&](int s, int bsel) {                                           \
        const int k0 = s * KC;                                                    \
        uint32_t base = sb_u + (uint32_t)bsel * GSTAGE_EL * 2u;                   \
        _Pragma("unroll")                                                         \
        for (int a = 0; a < 4; a++) {                                             \
            _Pragma("unroll")                                                     \
            for (int t = 0; t < 4; t++) {                                         \
                int idx = tid + t * 128;                                          \
                int r   = idx >> 2;                                               \
                int c   = (idx & 3) * 8;                                          \
                uint32_t dst = base + (uint32_t)(a * GT_EL + r * PITCH + c) * 2u; \
                CP_ASYNC16(dst, srcs[a] + (size_t)r * K + k0 + c);                \
            }                                                                     \
        }                                                                         \
        CP_COMMIT();                                                              \
    };

// ============================================================================
// Merged QKV GEMM + fused qknorm/split/relayout epilogue (round-10 proven).
// ============================================================================
__global__ __launch_bounds__(128, 2)
void gemm_qkv(const __nv_bfloat16* __restrict__ Ah, const __nv_bfloat16* __restrict__ Al,
              const __nv_bfloat16* __restrict__ Wh, const __nv_bfloat16* __restrict__ Wl,
              const float* __restrict__ q_b, const float* __restrict__ kv_b,
              const float* __restrict__ gq, const float* __restrict__ gk)
{
    __shared__ __align__(16) __nv_bfloat16 sbuf[2 * GSTAGE_EL];

    const int K = HID;
    const int tid  = threadIdx.x;
    const int wid  = tid >> 5;
    const int lane = tid & 31;
    const int row0 = blockIdx.y * 128;
    const int col0 = blockIdx.x * 128;
    const int wm   = (wid >> 1) * 64;
    const int wn   = (wid & 1) * 64;

    const uint32_t sb_u = smem_u32(sbuf);
    const __nv_bfloat16* srcs[4] = {
        Ah + (size_t)row0 * K, Al + (size_t)row0 * K,
        Wh + (size_t)col0 * K, Wl + (size_t)col0 * K };

    const int NS = K / KC;
    GEMM_ISSUE_DEF

    issue(0, 0);
    issue(1, 1);

    const int a_row = lane & 15;
    const int a_k   = (lane >> 4) << 3;
    const int b_n   = (lane & 7) + ((lane >> 4) << 3);
    const int b_k   = lane & 8;

    float acc[4][8][4];
#pragma unroll
    for (int mt = 0; mt < 4; mt++)
#pragma unroll
        for (int nt = 0; nt < 8; nt++)
#pragma unroll
            for (int r = 0; r < 4; r++) acc[mt][nt][r] = 0.f;

    GEMM_MAINLOOP64(acc)

    const int g  = lane >> 2;
    const int t2 = (lane & 3) * 2;

#pragma unroll
    for (int nt = 0; nt < 8; nt++) {
        int col = col0 + wn + nt * 8 + t2;
        float b0 = (col < HID) ? __ldg(&q_b[col])     : __ldg(&kv_b[col - HID]);
        float b1 = (col + 1 < HID) ? __ldg(&q_b[col + 1]) : __ldg(&kv_b[col + 1 - HID]);
#pragma unroll
        for (int mt = 0; mt < 4; mt++) {
            acc[mt][nt][0] += b0; acc[mt][nt][1] += b1;
            acc[mt][nt][2] += b0; acc[mt][nt][3] += b1;
        }
    }

    const int seg = (col0 < HID) ? 0 : (col0 < 2 * HID) ? 1 : 2;
    const int h   = ((col0 & (HID - 1)) + wn) >> 6;
    __nv_bfloat16* dh = (seg == 0) ? g_qh : (seg == 1) ? g_kh : g_vh;
    __nv_bfloat16* dl = (seg == 0) ? g_ql : (seg == 1) ? g_kl : g_vl;
    const float* gamma = (seg == 0) ? gq : gk;

#pragma unroll
    for (int mt = 0; mt < 4; mt++) {
#pragma unroll
        for (int rh = 0; rh < 2; rh++) {
            float inv = 1.0f;
            if (seg < 2) {
                float ssum = 0.f;
#pragma unroll
                for (int nt = 0; nt < 8; nt++) {
                    float v0 = acc[mt][nt][rh * 2 + 0];
                    float v1 = acc[mt][nt][rh * 2 + 1];
                    ssum += v0 * v0 + v1 * v1;
                }
                ssum += __shfl_xor_sync(0xffffffffu, ssum, 1);
                ssum += __shfl_xor_sync(0xffffffffu, ssum, 2);
                inv = 8.0f / fmaxf(sqrtf(ssum), 1e-12f);
            }
            int row  = row0 + wm + mt * 16 + g + rh * 8;
            int b    = row >> 11;
            int srow = row & (SS - 1);
            size_t base = ((size_t)(b * NH + h) * SS + srow) * HD;
#pragma unroll
            for (int nt = 0; nt < 8; nt++) {
                int d = nt * 8 + t2;
                float g0 = 1.f, g1 = 1.f;
                if (seg < 2) {
                    g0 = __ldg(&gamma[h * HD + d]);
                    g1 = __ldg(&gamma[h * HD + d + 1]);
                }
                float v0 = acc[mt][nt][rh * 2 + 0] * inv * g0;
                float v1 = acc[mt][nt][rh * 2 + 1] * inv * g1;
                uint32_t hi, lo;
                bf16_split2(v0, v1, hi, lo);
                *reinterpret_cast<uint32_t*>(&dh[base + d]) = hi;
                *reinterpret_cast<uint32_t*>(&dl[base + d]) = lo;
            }
        }
    }
}

// ============================================================================
// Out-proj GEMM (fp32 out), 4 warps, 64x64 warp tile (round-10 proven).
// ============================================================================
__global__ __launch_bounds__(128, 2)
void gemm_pre(const __nv_bfloat16* __restrict__ Ah, const __nv_bfloat16* __restrict__ Al,
              const __nv_bfloat16* __restrict__ Wh, const __nv_bfloat16* __restrict__ Wl,
              float* __restrict__ C, int M, int N, int K)
{
    __shared__ __align__(16) __nv_bfloat16 sbuf[2 * GSTAGE_EL];

    const int tid  = threadIdx.x;
    const int wid  = tid >> 5;
    const int lane = tid & 31;
    const int row0 = blockIdx.y * 128;
    const int col0 = blockIdx.x * 128;
    const int wm   = (wid >> 1) * 64;
    const int wn   = (wid & 1) * 64;

    const uint32_t sb_u = smem_u32(sbuf);
    const __nv_bfloat16* srcs[4] = {
        Ah + (size_t)row0 * K, Al + (size_t)row0 * K,
        Wh + (size_t)col0 * K, Wl + (size_t)col0 * K };

    const int NS = K / KC;
    GEMM_ISSUE_DEF

    issue(0, 0);
    issue(1, 1);

    const int a_row = lane & 15;
    const int a_k   = (lane >> 4) << 3;
    const int b_n   = (lane & 7) + ((lane >> 4) << 3);
    const int b_k   = lane & 8;

    float acc[4][8][4];
#pragma unroll
    for (int mt = 0; mt < 4; mt++)
#pragma unroll
        for (int nt = 0; nt < 8; nt++)
#pragma unroll
            for (int r = 0; r < 4; r++) acc[mt][nt][r] = 0.f;

    GEMM_MAINLOOP64(acc)

    const int g  = lane >> 2;
    const int t2 = (lane & 3) * 2;
#pragma unroll
    for (int mt = 0; mt < 4; mt++) {
#pragma unroll
        for (int nt = 0; nt < 8; nt++) {
            int row = row0 + wm + mt * 16 + g;
            int col = col0 + wn + nt * 8 + t2;
            *reinterpret_cast<float2*>(&C[(size_t)row * N + col]) =
                make_float2(acc[mt][nt][0], acc[mt][nt][1]);
            *reinterpret_cast<float2*>(&C[(size_t)(row + 8) * N + col]) =
                make_float2(acc[mt][nt][2], acc[mt][nt][3]);
        }
    }
}

// ============================================================================
// Tensor-core flash attention: 4 warps x 32 query rows (round-10 base),
// with Q_hi fragments HOISTED into registers across the KV loop
// (Q_lo still reloaded per ks to cap register liveness).
// ============================================================================
#define APITCH 72
#define QTILE_EL  (128 * APITCH)
#define KVARR_EL  (64 * APITCH)
#define BUF_EL    (4 * KVARR_EL)
#define ATT_SMEM  ((2 * QTILE_EL + 2 * BUF_EL) * 2)   // 110592 bytes
#define NT        (SS / 64)

__global__ __launch_bounds__(128, 2)
void attn_mma(const __nv_bfloat16* __restrict__ qh, const __nv_bfloat16* __restrict__ ql,
              const __nv_bfloat16* __restrict__ kh, const __nv_bfloat16* __restrict__ kl,
              const __nv_bfloat16* __restrict__ vh, const __nv_bfloat16* __restrict__ vl,
              __nv_bfloat16* __restrict__ aoh, __nv_bfloat16* __restrict__ aol)
{
    extern __shared__ __nv_bfloat16 sm[];
    __nv_bfloat16* Qh = sm;
    __nv_bfloat16* Ql = Qh + QTILE_EL;
    __nv_bfloat16* Bf = Ql + QTILE_EL;

    const int tid  = threadIdx.x;
    const int wid  = tid >> 5;
    const int lane = tid & 31;
    const int bh   = blockIdx.y;
    const int q0   = blockIdx.x * 128;
    const int wm   = wid * 32;
    const size_t bh_off = (size_t)bh * SS * HD;

    const __nv_bfloat16* srcs[4] = {kh + bh_off, kl + bh_off, vh + bh_off, vl + bh_off};
    const uint32_t buf_u[2] = { smem_u32(Bf), smem_u32(Bf + BUF_EL) };
    const uint32_t Qh_u = smem_u32(Qh);
    const uint32_t Ql_u = smem_u32(Ql);

    auto issue = [&](int kt, int bsel) {
#pragma unroll
        for (int i = 0; i < 16; i++) {
            const __nv_bfloat16* sp = srcs[i >> 2];
            int rem = ((i & 3) << 7) + tid;
            int r = rem >> 3;
            int c = (rem & 7) * 8;
            uint32_t dst = buf_u[bsel] + (uint32_t)((i >> 2) * KVARR_EL + r * APITCH + c) * 2u;
            CP_ASYNC16(dst, sp + (size_t)(kt * 64 + r) * HD + c);
        }
        CP_COMMIT();
    };

    issue(0, 0);
    issue(1, 1);

    {
        const __nv_bfloat16* qsrc[2] = {qh + bh_off, ql + bh_off};
        __nv_bfloat16* qdst[2] = {Qh, Ql};
#pragma unroll
        for (int i = 0; i < 16; i++) {
            int rem = ((i & 7) << 7) + tid;
            int r = rem >> 3;
            int c = (rem & 7) * 8;
            uint4 v = *reinterpret_cast<const uint4*>(
                qsrc[i >> 3] + (size_t)(q0 + r) * HD + c);
            *reinterpret_cast<uint4*>(qdst[i >> 3] + r * APITCH + c) = v;
        }
    }
    __syncthreads();

    const int a_row = lane & 15;
    const int a_k   = (lane >> 4) << 3;
    const int b_n   = (lane & 7) + ((lane >> 4) << 3);
    const int b_k   = lane & 8;

    // ---- hoist Q_hi fragments (32 regs), kept live across the KV loop ----
    uint32_t qfhH[4][2][4];
#pragma unroll
    for (int ks = 0; ks < 4; ks++)
#pragma unroll
        for (int mt = 0; mt < 2; mt++) {
            uint32_t off = (uint32_t)((wm + mt * 16 + a_row) * APITCH + ks * 16 + a_k) * 2u;
            LDM_X4(qfhH[ks][mt][0], qfhH[ks][mt][1], qfhH[ks][mt][2], qfhH[ks][mt][3],
                   Qh_u + off);
        }

    float m_run[2][2], l_run[2][2];
    float O[2][8][4];
#pragma unroll
    for (int mt = 0; mt < 2; mt++) {
        m_run[mt][0] = -1e30f; m_run[mt][1] = -1e30f;
        l_run[mt][0] = 0.f;    l_run[mt][1] = 0.f;
#pragma unroll
        for (int d = 0; d < 8; d++)
#pragma unroll
            for (int r = 0; r < 4; r++) O[mt][d][r] = 0.f;
    }

    for (int t = 0; t < NT; t++) {
        if (t < NT - 1) { CP_WAIT1(); } else { CP_WAIT0(); }
        __syncthreads();

        const uint32_t Ks_h = buf_u[t & 1];
        const uint32_t Ks_l = Ks_h + KVARR_EL * 2u;
        const uint32_t Vs_h = Ks_h + 2u * KVARR_EL * 2u;
        const uint32_t Vs_l = Ks_h + 3u * KVARR_EL * 2u;

        float S[2][8][4];
#pragma unroll
        for (int mt = 0; mt < 2; mt++)
#pragma unroll
            for (int nt = 0; nt < 8; nt++)
#pragma unroll
                for (int r = 0; r < 4; r++) S[mt][nt][r] = 0.f;

#pragma unroll
        for (int ks = 0; ks < 4; ks++) {
            uint32_t kfh[4][4], kfl[4][4];
#pragma unroll
            for (int p = 0; p < 4; p++) {
                uint32_t off = (uint32_t)((p * 16 + b_n) * APITCH + ks * 16 + b_k) * 2u;
                LDM_X4(kfh[p][0], kfh[p][1], kfh[p][2], kfh[p][3], Ks_h + off);
                LDM_X4(kfl[p][0], kfl[p][1], kfl[p][2], kfl[p][3], Ks_l + off);
            }
            uint32_t qfl[2][4];
#pragma unroll
            for (int mt = 0; mt < 2; mt++) {
                uint32_t off = (uint32_t)((wm + mt * 16 + a_row) * APITCH + ks * 16 + a_k) * 2u;
                LDM_X4(qfl[mt][0], qfl[mt][1], qfl[mt][2], qfl[mt][3], Ql_u + off);
            }
#pragma unroll
            for (int mt = 0; mt < 2; mt++)
#pragma unroll
                for (int nt = 0; nt < 8; nt++) {
                    int p = nt >> 1, o = (nt & 1) * 2;
                    MMA_BF16(S[mt][nt], qfhH[ks][mt], kfh[p][o], kfh[p][o+1]);
                }
#pragma unroll
            for (int mt = 0; mt < 2; mt++)
#pragma unroll
                for (int nt = 0; nt < 8; nt++) {
                    int p = nt >> 1, o = (nt & 1) * 2;
                    MMA_BF16(S[mt][nt], qfhH[ks][mt], kfl[p][o], kfl[p][o+1]);
                }
#pragma unroll
            for (int mt = 0; mt < 2; mt++)
#pragma unroll
                for (int nt = 0; nt < 8; nt++) {
                    int p = nt >> 1, o = (nt & 1) * 2;
                    MMA_BF16(S[mt][nt], qfl[mt], kfh[p][o], kfh[p][o+1]);
                }
        }

#pragma unroll
        for (int mt = 0; mt < 2; mt++) {
            float mx0 = -1e30f, mx1 = -1e30f;
#pragma unroll
            for (int nt = 0; nt < 8; nt++) {
                mx0 = fmaxf(mx0, fmaxf(S[mt][nt][0], S[mt][nt][1]));
                mx1 = fmaxf(mx1, fmaxf(S[mt][nt][2], S[mt][nt][3]));
            }
            mx0 = fmaxf(mx0, __shfl_xor_sync(0xffffffffu, mx0, 1));
            mx0 = fmaxf(mx0, __shfl_xor_sync(0xffffffffu, mx0, 2));
            mx1 = fmaxf(mx1, __shfl_xor_sync(0xffffffffu, mx1, 1));
            mx1 = fmaxf(mx1, __shfl_xor_sync(0xffffffffu, mx1, 2));
            float mn0 = fmaxf(m_run[mt][0], mx0), mn1 = fmaxf(m_run[mt][1], mx1);
            float c0 = __expf(m_run[mt][0] - mn0), c1 = __expf(m_run[mt][1] - mn1);
            m_run[mt][0] = mn0; m_run[mt][1] = mn1;

            float s0 = 0.f, s1 = 0.f;
#pragma unroll
            for (int nt = 0; nt < 8; nt++) {
                S[mt][nt][0] = __expf(S[mt][nt][0] - mn0);
                S[mt][nt][1] = __expf(S[mt][nt][1] - mn0);
                S[mt][nt][2] = __expf(S[mt][nt][2] - mn1);
                S[mt][nt][3] = __expf(S[mt][nt][3] - mn1);
                s0 += S[mt][nt][0] + S[mt][nt][1];
                s1 += S[mt][nt][2] + S[mt][nt][3];
            }
            s0 += __shfl_xor_sync(0xffffffffu, s0, 1);
            s0 += __shfl_xor_sync(0xffffffffu, s0, 2);
            s1 += __shfl_xor_sync(0xffffffffu, s1, 1);
            s1 += __shfl_xor_sync(0xffffffffu, s1, 2);
            l_run[mt][0] = l_run[mt][0] * c0 + s0;
            l_run[mt][1] = l_run[mt][1] * c1 + s1;
#pragma unroll
            for (int d = 0; d < 8; d++) {
                O[mt][d][0] *= c0; O[mt][d][1] *= c0;
                O[mt][d][2] *= c1; O[mt][d][3] *= c1;
            }
        }

#pragma unroll
        for (int ks = 0; ks < 4; ks++) {
            uint32_t pfh[2][4], pfl[2][4];
#pragma unroll
            for (int mt = 0; mt < 2; mt++) {
                bf16_split2(S[mt][2*ks][0],   S[mt][2*ks][1],   pfh[mt][0], pfl[mt][0]);
                bf16_split2(S[mt][2*ks][2],   S[mt][2*ks][3],   pfh[mt][1], pfl[mt][1]);
                bf16_split2(S[mt][2*ks+1][0], S[mt][2*ks+1][1], pfh[mt][2], pfl[mt][2]);
                bf16_split2(S[mt][2*ks+1][2], S[mt][2*ks+1][3], pfh[mt][3], pfl[mt][3]);
            }
            uint32_t vfh[4][4], vfl[4][4];
#pragma unroll
            for (int pd = 0; pd < 4; pd++) {
                uint32_t off = (uint32_t)((ks * 16 + (lane & 15)) * APITCH +
                                          pd * 16 + ((lane >> 4) << 3)) * 2u;
                LDM_X4T(vfh[pd][0], vfh[pd][1], vfh[pd][2], vfh[pd][3], Vs_h + off);
                LDM_X4T(vfl[pd][0], vfl[pd][1], vfl[pd][2], vfl[pd][3], Vs_l + off);
            }
#pragma unroll
            for (int mt = 0; mt < 2; mt++)
#pragma unroll
                for (int dt = 0; dt < 8; dt++) {
                    int pd = dt >> 1, o = (dt & 1) * 2;
                    MMA_BF16(O[mt][dt], pfh[mt], vfh[pd][o], vfh[pd][o+1]);
                }
#pragma unroll
            for (int mt = 0; mt < 2; mt++)
#pragma unroll
                for (int dt = 0; dt < 8; dt++) {
                    int pd = dt >> 1, o = (dt & 1) * 2;
                    MMA_BF16(O[mt][dt], pfh[mt], vfl[pd][o], vfl[pd][o+1]);
                }
#pragma unroll
            for (int mt = 0; mt < 2; mt++)
#pragma unroll
                for (int dt = 0; dt < 8; dt++) {
                    int pd = dt >> 1, o = (dt & 1) * 2;
                    MMA_BF16(O[mt][dt], pfl[mt], vfh[pd][o], vfh[pd][o+1]);
                }
        }

        __syncthreads();
        if (t + 2 < NT) issue(t + 2, t & 1);
    }

    const int g  = lane >> 2;
    const int t2 = (lane & 3) * 2;
    const int b  = bh >> 4;
    const int h  = bh & 15;
#pragma unroll
    for (int mt = 0; mt < 2; mt++) {
        float inv0 = 1.0f / l_run[mt][0], inv1 = 1.0f / l_run[mt][1];
        int row = b * SS + q0 + wm + mt * 16 + g;
#pragma unroll
        for (int dt = 0; dt < 8; dt++) {
            int col = h * HD + dt * 8 + t2;
            uint32_t hi, lo;
            bf16_split2(O[mt][dt][0] * inv0, O[mt][dt][1] * inv0, hi, lo);
            *reinterpret_cast<uint32_t*>(&aoh[(size_t)row * HID + col]) = hi;
            *reinterpret_cast<uint32_t*>(&aol[(size_t)row * HID + col]) = lo;
            bf16_split2(O[mt][dt][2] * inv1, O[mt][dt][3] * inv1, hi, lo);
            *reinterpret_cast<uint32_t*>(&aoh[(size_t)(row + 8) * HID + col]) = hi;
            *reinterpret_cast<uint32_t*>(&aol[(size_t)(row + 8) * HID + col]) = lo;
        }
    }
}

// ----------------------------------------------------------------------------
// Launch
// ----------------------------------------------------------------------------
extern "C" void kernel_launch(void* const* d_in, const int* in_sizes, int n_in,
                              void* d_out, int out_size)
{
    const float* x     = (const float*)d_in[0];
    const float* q_w   = (const float*)d_in[1];
    const float* q_b   = (const float*)d_in[2];
    const float* kv_w  = (const float*)d_in[3];
    const float* kv_b  = (const float*)d_in[4];
    const float* gq    = (const float*)d_in[5];
    const float* gk    = (const float*)d_in[6];
    const float* out_w = (const float*)d_in[7];
    float* out = (float*)d_out;

    __nv_bfloat16 *pqh, *pql, *pkh, *pkl, *pvh, *pvl;
    cudaGetSymbolAddress((void**)&pqh, g_qh);
    cudaGetSymbolAddress((void**)&pql, g_ql);
    cudaGetSymbolAddress((void**)&pkh, g_kh);
    cudaGetSymbolAddress((void**)&pkl, g_kl);
    cudaGetSymbolAddress((void**)&pvh, g_vh);
    cudaGetSymbolAddress((void**)&pvl, g_vl);
    __nv_bfloat16 *pxh, *pxl, *paoh, *paol, *pwh, *pwl, *powh, *powl;
    cudaGetSymbolAddress((void**)&pxh,  g_xh);
    cudaGetSymbolAddress((void**)&pxl,  g_xl);
    cudaGetSymbolAddress((void**)&paoh, g_aoh);
    cudaGetSymbolAddress((void**)&paol, g_aol);
    cudaGetSymbolAddress((void**)&pwh,  g_wh);
    cudaGetSymbolAddress((void**)&pwl,  g_wl);
    cudaGetSymbolAddress((void**)&powh, g_owh);
    cudaGetSymbolAddress((void**)&powl, g_owl);

    cudaFuncSetAttribute(attn_mma,
                         cudaFuncAttributeMaxDynamicSharedMemorySize, ATT_SMEM);

    // Pre-split inputs + all weights (one launch)
    split_all<<<(NSPLIT4 + 255) / 256, 256>>>(x, q_w, kv_w, out_w);

    // Merged QKV projection + fused qknorm/split/relayout (4 warps/CTA)
    {
        dim3 grid((3 * HID) / 128, MR / 128);   // (24, 64)
        gemm_qkv<<<grid, 128>>>(pxh, pxl, pwh, pwl, q_b, kv_b, gq, gk);
    }
    // Attention (tensor cores, 128 queries/CTA, 4 warps x 32 rows, 2 CTA/SM)
    {
        dim3 grid(SS / 128, BB * NH);           // (16, 64)
        attn_mma<<<grid, 128, ATT_SMEM>>>(pqh, pql, pkh, pkl, pvh, pvl, paoh, paol);
    }
    // Output projection (4 warps/CTA)
    {
        dim3 grid(HID / 128, MR / 128);
        gemm_pre<<<grid, 128>>>(paoh, paol, powh, powl, out, MR, HID, HID);
    }
}

// round 15
// speedup vs baseline: 1.0836x; 1.0248x over previous
#include <cuda_runtime.h>
#include <cuda_bf16.h>
#include <math.h>
#include <stdint.h>

// Problem constants
#define BB   4
#define SS   2048
#define HID  1024
#define NH   16
#define HD   64
#define MR   (BB*SS)   // 8192 rows

// Pre-split bf16 operands for attention, layout [b][h][s][64]
__device__ __nv_bfloat16 g_qh[(size_t)MR * HID];
__device__ __nv_bfloat16 g_ql[(size_t)MR * HID];
__device__ __nv_bfloat16 g_kh[(size_t)MR * HID];
__device__ __nv_bfloat16 g_kl[(size_t)MR * HID];
__device__ __nv_bfloat16 g_vh[(size_t)MR * HID];
__device__ __nv_bfloat16 g_vl[(size_t)MR * HID];
// Pre-split GEMM operands
__device__ __nv_bfloat16 g_xh [(size_t)MR * HID];
__device__ __nv_bfloat16 g_xl [(size_t)MR * HID];
__device__ __nv_bfloat16 g_aoh[(size_t)MR * HID];
__device__ __nv_bfloat16 g_aol[(size_t)MR * HID];
__device__ __nv_bfloat16 g_wh [(size_t)3 * HID * HID];   // concat(q_w, kv_w)
__device__ __nv_bfloat16 g_wl [(size_t)3 * HID * HID];
__device__ __nv_bfloat16 g_owh[(size_t)HID * HID];
__device__ __nv_bfloat16 g_owl[(size_t)HID * HID];

__device__ __forceinline__ uint32_t smem_u32(const void* p) {
    uint32_t a;
    asm("{ .reg .u64 t; cvta.to.shared.u64 t, %1; cvt.u32.u64 %0, t; }"
        : "=r"(a) : "l"(p));
    return a;
}

__device__ __forceinline__ void bf16_split2(float x, float y,
                                            uint32_t& hi, uint32_t& lo) {
    __nv_bfloat16 hx = __float2bfloat16(x);
    __nv_bfloat16 hy = __float2bfloat16(y);
    __nv_bfloat16 lx = __float2bfloat16(x - __bfloat162float(hx));
    __nv_bfloat16 ly = __float2bfloat16(y - __bfloat162float(hy));
    __nv_bfloat162 h; h.x = hx; h.y = hy;
    __nv_bfloat162 l; l.x = lx; l.y = ly;
    hi = *reinterpret_cast<uint32_t*>(&h);
    lo = *reinterpret_cast<uint32_t*>(&l);
}

#define LDM_X4(r0, r1, r2, r3, addr) \
    asm volatile("ldmatrix.sync.aligned.m8n8.x4.shared.b16 {%0,%1,%2,%3}, [%4];" \
                 : "=r"(r0), "=r"(r1), "=r"(r2), "=r"(r3) : "r"(addr))
#define LDM_X4T(r0, r1, r2, r3, addr) \
    asm volatile("ldmatrix.sync.aligned.m8n8.x4.trans.shared.b16 {%0,%1,%2,%3}, [%4];" \
                 : "=r"(r0), "=r"(r1), "=r"(r2), "=r"(r3) : "r"(addr))

#define MMA_BF16(d, a, b0v, b1v) \
    asm volatile("mma.sync.aligned.m16n8k16.row.col.f32.bf16.bf16.f32 " \
                 "{%0,%1,%2,%3}, {%4,%5,%6,%7}, {%8,%9}, {%0,%1,%2,%3};" \
                 : "+f"((d)[0]), "+f"((d)[1]), "+f"((d)[2]), "+f"((d)[3]) \
                 : "r"((a)[0]), "r"((a)[1]), "r"((a)[2]), "r"((a)[3]), \
                   "r"(b0v), "r"(b1v))

#define CP_ASYNC16(dst, src) \
    asm volatile("cp.async.cg.shared.global [%0], [%1], 16;" \
                 :: "r"(dst), "l"(src) : "memory")
#define CP_COMMIT() asm volatile("cp.async.commit_group;" ::: "memory")
#define CP_WAIT1()  asm volatile("cp.async.wait_group 1;" ::: "memory")
#define CP_WAIT0()  asm volatile("cp.async.wait_group 0;" ::: "memory")

// ============================================================================
// Merged split: fp32 -> bf16 hi/lo, 4 float4 chunks per thread (MLP=4)
// ============================================================================
#define NX4   (MR * HID / 4)
#define NQW4  (HID * HID / 4)
#define NKVW4 (2 * HID * HID / 4)
#define NOW4  (HID * HID / 4)
#define NSPLIT4 (NX4 + NQW4 + NKVW4 + NOW4)
#define NSPLIT16 (NSPLIT4 / 4)

__global__ __launch_bounds__(256)
void split_all(const float* __restrict__ x, const float* __restrict__ qw,
               const float* __restrict__ kvw, const float* __restrict__ ow)
{
    int i = blockIdx.x * blockDim.x + threadIdx.x;
    if (i >= NSPLIT16) return;
    int c0 = i * 4;                 // first float4-chunk id; all 4 in same array
    const float* src;
    __nv_bfloat16 *dh, *dl;
    int off;
    if (c0 < NX4) {
        src = x; dh = g_xh; dl = g_xl; off = c0;
    } else if (c0 < NX4 + NQW4) {
        src = qw; dh = g_wh; dl = g_wl; off = c0 - NX4;
    } else if (c0 < NX4 + NQW4 + NKVW4) {
        src = kvw; off = c0 - NX4 - NQW4;
        dh = g_wh + (size_t)HID * HID; dl = g_wl + (size_t)HID * HID;
    } else {
        src = ow; dh = g_owh; dl = g_owl; off = c0 - NX4 - NQW4 - NKVW4;
    }
    float4 v[4];
#pragma unroll
    for (int j = 0; j < 4; j++)
        v[j] = *reinterpret_cast<const float4*>(src + (size_t)(off + j) * 4);
#pragma unroll
    for (int j = 0; j < 4; j++) {
        uint32_t h0, l0, h1, l1;
        bf16_split2(v[j].x, v[j].y, h0, l0);
        bf16_split2(v[j].z, v[j].w, h1, l1);
        *reinterpret_cast<uint2*>(dh + (size_t)(off + j) * 4) = make_uint2(h0, h1);
        *reinterpret_cast<uint2*>(dl + (size_t)(off + j) * 4) = make_uint2(l0, l1);
    }
}

// ============================================================================
// Shared GEMM pieces: 4 warps/CTA, warp tile 64m x 64n, CTA tile 128x128,
// 2 CTA/SM (round-10 proven configuration, byte-identical).
// ============================================================================
#define KC    32
#define PITCH 40
#define GT_EL (128 * PITCH)
#define GSTAGE_EL (4 * GT_EL)

#define GEMM_MAINLOOP64(acc)                                                      \
    for (int s = 0; s < NS; s++) {                                                \
        if (s < NS - 1) { CP_WAIT1(); } else { CP_WAIT0(); }                      \
        __syncthreads();                                                          \
        const uint32_t bAh = sb_u + (uint32_t)((s & 1) * GSTAGE_EL) * 2u;         \
        const uint32_t bAl = bAh + (uint32_t)GT_EL * 2u;                          \
        const uint32_t bBh = bAh + (uint32_t)(2 * GT_EL) * 2u;                    \
        const uint32_t bBl = bAh + (uint32_t)(3 * GT_EL) * 2u;                    \
        _Pragma("unroll")                                                         \
        for (int kk = 0; kk < KC; kk += 16) {                                     \
            uint32_t bh[16], bl[16];                                              \
            _Pragma("unroll")                                                     \
            for (int p = 0; p < 4; p++) {                                         \
                uint32_t off = (uint32_t)((wn + p * 16 + b_n) * PITCH + kk + b_k) * 2u; \
                LDM_X4(bh[p*4+0], bh[p*4+1], bh[p*4+2], bh[p*4+3], bBh + off);    \
                LDM_X4(bl[p*4+0], bl[p*4+1], bl[p*4+2], bl[p*4+3], bBl + off);    \
            }                                                                     \
            uint32_t ah[4][4], al[4][4];                                          \
            _Pragma("unroll")                                                     \
            for (int mt = 0; mt < 4; mt++) {                                      \
                uint32_t off = (uint32_t)((wm + mt * 16 + a_row) * PITCH + kk + a_k) * 2u; \
                LDM_X4(ah[mt][0], ah[mt][1], ah[mt][2], ah[mt][3], bAh + off);    \
                LDM_X4(al[mt][0], al[mt][1], al[mt][2], al[mt][3], bAl + off);    \
            }                                                                     \
            _Pragma("unroll")                                                     \
            for (int mt = 0; mt < 4; mt++)                                        \
                _Pragma("unroll")                                                 \
                for (int nt = 0; nt < 8; nt++) {                                  \
                    int p = nt >> 1, o = (nt & 1) * 2;                            \
                    MMA_BF16(acc[mt][nt], ah[mt], bh[p*4+o], bh[p*4+o+1]);        \
                }                                                                 \
            _Pragma("unroll")                                                     \
            for (int mt = 0; mt < 4; mt++)                                        \
                _Pragma("unroll")                                                 \
                for (int nt = 0; nt < 8; nt++) {                                  \
                    int p = nt >> 1, o = (nt & 1) * 2;                            \
                    MMA_BF16(acc[mt][nt], ah[mt], bl[p*4+o], bl[p*4+o+1]);        \
                }                                                                 \
            _Pragma("unroll")                                                     \
            for (int mt = 0; mt < 4; mt++)                                        \
                _Pragma("unroll")                                                 \
                for (int nt = 0; nt < 8; nt++) {                                  \
                    int p = nt >> 1, o = (nt & 1) * 2;                            \
                    MMA_BF16(acc[mt][nt], al[mt], bh[p*4+o], bh[p*4+o+1]);        \
                }                                                                 \
        }                                                                         \
        __syncthreads();                                                          \
        if (s + 2 < NS) issue(s + 2, s & 1);                                      \
    }

#define GEMM_ISSUE_DEF                                                            \
    auto issue = [&](int s, int bsel) {                                           \
        const int k0 = s * KC;                                                    \
        uint32_t base = sb_u + (uint32_t)bsel * GSTAGE_EL * 2u;                   \
        _Pragma("unroll")                                                         \
        for (int a = 0; a < 4; a++) {                                             \
            _Pragma("unroll")                                                     \
            for (int t = 0; t < 4; t++) {                                         \
                int idx = tid + t * 128;                                          \
                int r   = idx >> 2;                                               \
                int c   = (idx & 3) * 8;                                          \
                uint32_t dst = base + (uint32_t)(a * GT_EL + r * PITCH + c) * 2u; \
                CP_ASYNC16(dst, srcs[a] + (size_t)r * K + k0 + c);                \
            }                                                                     \
        }                                                                         \
        CP_COMMIT();                                                              \
    };

// ============================================================================
// Merged QKV GEMM + fused qknorm/split/relayout epilogue (round-10 proven).
// ============================================================================
__global__ __launch_bounds__(128, 2)
void gemm_qkv(const __nv_bfloat16* __restrict__ Ah, const __nv_bfloat16* __restrict__ Al,
              const __nv_bfloat16* __restrict__ Wh, const __nv_bfloat16* __restrict__ Wl,
              const float* __restrict__ q_b, const float* __restrict__ kv_b,
              const float* __restrict__ gq, const float* __restrict__ gk)
{
    __shared__ __align__(16) __nv_bfloat16 sbuf[2 * GSTAGE_EL];

    const int K = HID;
    const int tid  = threadIdx.x;
    const int wid  = tid >> 5;
    const int lane = tid & 31;
    const int row0 = blockIdx.y * 128;
    const int col0 = blockIdx.x * 128;
    const int wm   = (wid >> 1) * 64;
    const int wn   = (wid & 1) * 64;

    const uint32_t sb_u = smem_u32(sbuf);
    const __nv_bfloat16* srcs[4] = {
        Ah + (size_t)row0 * K, Al + (size_t)row0 * K,
        Wh + (size_t)col0 * K, Wl + (size_t)col0 * K };

    const int NS = K / KC;
    GEMM_ISSUE_DEF

    issue(0, 0);
    issue(1, 1);

    const int a_row = lane & 15;
    const int a_k   = (lane >> 4) << 3;
    const int b_n   = (lane & 7) + ((lane >> 4) << 3);
    const int b_k   = lane & 8;

    float acc[4][8][4];
#pragma unroll
    for (int mt = 0; mt < 4; mt++)
#pragma unroll
        for (int nt = 0; nt < 8; nt++)
#pragma unroll
            for (int r = 0; r < 4; r++) acc[mt][nt][r] = 0.f;

    GEMM_MAINLOOP64(acc)

    const int g  = lane >> 2;
    const int t2 = (lane & 3) * 2;

#pragma unroll
    for (int nt = 0; nt < 8; nt++) {
        int col = col0 + wn + nt * 8 + t2;
        float b0 = (col < HID) ? __ldg(&q_b[col])     : __ldg(&kv_b[col - HID]);
        float b1 = (col + 1 < HID) ? __ldg(&q_b[col + 1]) : __ldg(&kv_b[col + 1 - HID]);
#pragma unroll
        for (int mt = 0; mt < 4; mt++) {
            acc[mt][nt][0] += b0; acc[mt][nt][1] += b1;
            acc[mt][nt][2] += b0; acc[mt][nt][3] += b1;
        }
    }

    const int seg = (col0 < HID) ? 0 : (col0 < 2 * HID) ? 1 : 2;
    const int h   = ((col0 & (HID - 1)) + wn) >> 6;
    __nv_bfloat16* dh = (seg == 0) ? g_qh : (seg == 1) ? g_kh : g_vh;
    __nv_bfloat16* dl = (seg == 0) ? g_ql : (seg == 1) ? g_kl : g_vl;
    const float* gamma = (seg == 0) ? gq : gk;

#pragma unroll
    for (int mt = 0; mt < 4; mt++) {
#pragma unroll
        for (int rh = 0; rh < 2; rh++) {
            float inv = 1.0f;
            if (seg < 2) {
                float ssum = 0.f;
#pragma unroll
                for (int nt = 0; nt < 8; nt++) {
                    float v0 = acc[mt][nt][rh * 2 + 0];
                    float v1 = acc[mt][nt][rh * 2 + 1];
                    ssum += v0 * v0 + v1 * v1;
                }
                ssum += __shfl_xor_sync(0xffffffffu, ssum, 1);
                ssum += __shfl_xor_sync(0xffffffffu, ssum, 2);
                inv = 8.0f / fmaxf(sqrtf(ssum), 1e-12f);
            }
            int row  = row0 + wm + mt * 16 + g + rh * 8;
            int b    = row >> 11;
            int srow = row & (SS - 1);
            size_t base = ((size_t)(b * NH + h) * SS + srow) * HD;
#pragma unroll
            for (int nt = 0; nt < 8; nt++) {
                int d = nt * 8 + t2;
                float g0 = 1.f, g1 = 1.f;
                if (seg < 2) {
                    g0 = __ldg(&gamma[h * HD + d]);
                    g1 = __ldg(&gamma[h * HD + d + 1]);
                }
                float v0 = acc[mt][nt][rh * 2 + 0] * inv * g0;
                float v1 = acc[mt][nt][rh * 2 + 1] * inv * g1;
                uint32_t hi, lo;
                bf16_split2(v0, v1, hi, lo);
                *reinterpret_cast<uint32_t*>(&dh[base + d]) = hi;
                *reinterpret_cast<uint32_t*>(&dl[base + d]) = lo;
            }
        }
    }
}

// ============================================================================
// Out-proj GEMM (fp32 out), 4 warps, 64x64 warp tile (round-10 proven).
// ============================================================================
__global__ __launch_bounds__(128, 2)
void gemm_pre(const __nv_bfloat16* __restrict__ Ah, const __nv_bfloat16* __restrict__ Al,
              const __nv_bfloat16* __restrict__ Wh, const __nv_bfloat16* __restrict__ Wl,
              float* __restrict__ C, int M, int N, int K)
{
    __shared__ __align__(16) __nv_bfloat16 sbuf[2 * GSTAGE_EL];

    const int tid  = threadIdx.x;
    const int wid  = tid >> 5;
    const int lane = tid & 31;
    const int row0 = blockIdx.y * 128;
    const int col0 = blockIdx.x * 128;
    const int wm   = (wid >> 1) * 64;
    const int wn   = (wid & 1) * 64;

    const uint32_t sb_u = smem_u32(sbuf);
    const __nv_bfloat16* srcs[4] = {
        Ah + (size_t)row0 * K, Al + (size_t)row0 * K,
        Wh + (size_t)col0 * K, Wl + (size_t)col0 * K };

    const int NS = K / KC;
    GEMM_ISSUE_DEF

    issue(0, 0);
    issue(1, 1);

    const int a_row = lane & 15;
    const int a_k   = (lane >> 4) << 3;
    const int b_n   = (lane & 7) + ((lane >> 4) << 3);
    const int b_k   = lane & 8;

    float acc[4][8][4];
#pragma unroll
    for (int mt = 0; mt < 4; mt++)
#pragma unroll
        for (int nt = 0; nt < 8; nt++)
#pragma unroll
            for (int r = 0; r < 4; r++) acc[mt][nt][r] = 0.f;

    GEMM_MAINLOOP64(acc)

    const int g  = lane >> 2;
    const int t2 = (lane & 3) * 2;
#pragma unroll
    for (int mt = 0; mt < 4; mt++) {
#pragma unroll
        for (int nt = 0; nt < 8; nt++) {
            int row = row0 + wm + mt * 16 + g;
            int col = col0 + wn + nt * 8 + t2;
            *reinterpret_cast<float2*>(&C[(size_t)row * N + col]) =
                make_float2(acc[mt][nt][0], acc[mt][nt][1]);
            *reinterpret_cast<float2*>(&C[(size_t)(row + 8) * N + col]) =
                make_float2(acc[mt][nt][2], acc[mt][nt][3]);
        }
    }
}

// ============================================================================
// Tensor-core flash attention: 4 warps x 32 query rows (round-10 proven,
// byte-identical: Q fragments reloaded from smem per ks, no hoisting).
// ============================================================================
#define APITCH 72
#define QTILE_EL  (128 * APITCH)
#define KVARR_EL  (64 * APITCH)
#define BUF_EL    (4 * KVARR_EL)
#define ATT_SMEM  ((2 * QTILE_EL + 2 * BUF_EL) * 2)   // 110592 bytes
#define NT        (SS / 64)

__global__ __launch_bounds__(128, 2)
void attn_mma(const __nv_bfloat16* __restrict__ qh, const __nv_bfloat16* __restrict__ ql,
              const __nv_bfloat16* __restrict__ kh, const __nv_bfloat16* __restrict__ kl,
              const __nv_bfloat16* __restrict__ vh, const __nv_bfloat16* __restrict__ vl,
              __nv_bfloat16* __restrict__ aoh, __nv_bfloat16* __restrict__ aol)
{
    extern __shared__ __nv_bfloat16 sm[];
    __nv_bfloat16* Qh = sm;
    __nv_bfloat16* Ql = Qh + QTILE_EL;
    __nv_bfloat16* Bf = Ql + QTILE_EL;

    const int tid  = threadIdx.x;
    const int wid  = tid >> 5;
    const int lane = tid & 31;
    const int bh   = blockIdx.y;
    const int q0   = blockIdx.x * 128;
    const int wm   = wid * 32;
    const size_t bh_off = (size_t)bh * SS * HD;

    const __nv_bfloat16* srcs[4] = {kh + bh_off, kl + bh_off, vh + bh_off, vl + bh_off};
    const uint32_t buf_u[2] = { smem_u32(Bf), smem_u32(Bf + BUF_EL) };
    const uint32_t Qh_u = smem_u32(Qh);
    const uint32_t Ql_u = smem_u32(Ql);

    auto issue = [&](int kt, int bsel) {
#pragma unroll
        for (int i = 0; i < 16; i++) {
            const __nv_bfloat16* sp = srcs[i >> 2];
            int rem = ((i & 3) << 7) + tid;
            int r = rem >> 3;
            int c = (rem & 7) * 8;
            uint32_t dst = buf_u[bsel] + (uint32_t)((i >> 2) * KVARR_EL + r * APITCH + c) * 2u;
            CP_ASYNC16(dst, sp + (size_t)(kt * 64 + r) * HD + c);
        }
        CP_COMMIT();
    };

    issue(0, 0);
    issue(1, 1);

    {
        const __nv_bfloat16* qsrc[2] = {qh + bh_off, ql + bh_off};
        __nv_bfloat16* qdst[2] = {Qh, Ql};
#pragma unroll
        for (int i = 0; i < 16; i++) {
            int rem = ((i & 7) << 7) + tid;
            int r = rem >> 3;
            int c = (rem & 7) * 8;
            uint4 v = *reinterpret_cast<const uint4*>(
                qsrc[i >> 3] + (size_t)(q0 + r) * HD + c);
            *reinterpret_cast<uint4*>(qdst[i >> 3] + r * APITCH + c) = v;
        }
    }
    __syncthreads();

    const int a_row = lane & 15;
    const int a_k   = (lane >> 4) << 3;
    const int b_n   = (lane & 7) + ((lane >> 4) << 3);
    const int b_k   = lane & 8;

    float m_run[2][2], l_run[2][2];
    float O[2][8][4];
#pragma unroll
    for (int mt = 0; mt < 2; mt++) {
        m_run[mt][0] = -1e30f; m_run[mt][1] = -1e30f;
        l_run[mt][0] = 0.f;    l_run[mt][1] = 0.f;
#pragma unroll
        for (int d = 0; d < 8; d++)
#pragma unroll
            for (int r = 0; r < 4; r++) O[mt][d][r] = 0.f;
    }

    for (int t = 0; t < NT; t++) {
        if (t < NT - 1) { CP_WAIT1(); } else { CP_WAIT0(); }
        __syncthreads();

        const uint32_t Ks_h = buf_u[t & 1];
        const uint32_t Ks_l = Ks_h + KVARR_EL * 2u;
        const uint32_t Vs_h = Ks_h + 2u * KVARR_EL * 2u;
        const uint32_t Vs_l = Ks_h + 3u * KVARR_EL * 2u;

        float S[2][8][4];
#pragma unroll
        for (int mt = 0; mt < 2; mt++)
#pragma unroll
            for (int nt = 0; nt < 8; nt++)
#pragma unroll
                for (int r = 0; r < 4; r++) S[mt][nt][r] = 0.f;

#pragma unroll
        for (int ks = 0; ks < 4; ks++) {
            uint32_t kfh[4][4], kfl[4][4];
#pragma unroll
            for (int p = 0; p < 4; p++) {
                uint32_t off = (uint32_t)((p * 16 + b_n) * APITCH + ks * 16 + b_k) * 2u;
                LDM_X4(kfh[p][0], kfh[p][1], kfh[p][2], kfh[p][3], Ks_h + off);
                LDM_X4(kfl[p][0], kfl[p][1], kfl[p][2], kfl[p][3], Ks_l + off);
            }
            uint32_t qfh[2][4], qfl[2][4];
#pragma unroll
            for (int mt = 0; mt < 2; mt++) {
                uint32_t off = (uint32_t)((wm + mt * 16 + a_row) * APITCH + ks * 16 + a_k) * 2u;
                LDM_X4(qfh[mt][0], qfh[mt][1], qfh[mt][2], qfh[mt][3], Qh_u + off);
                LDM_X4(qfl[mt][0], qfl[mt][1], qfl[mt][2], qfl[mt][3], Ql_u + off);
            }
#pragma unroll
            for (int mt = 0; mt < 2; mt++)
#pragma unroll
                for (int nt = 0; nt < 8; nt++) {
                    int p = nt >> 1, o = (nt & 1) * 2;
                    MMA_BF16(S[mt][nt], qfh[mt], kfh[p][o], kfh[p][o+1]);
                }
#pragma unroll
            for (int mt = 0; mt < 2; mt++)
#pragma unroll
                for (int nt = 0; nt < 8; nt++) {
                    int p = nt >> 1, o = (nt & 1) * 2;
                    MMA_BF16(S[mt][nt], qfh[mt], kfl[p][o], kfl[p][o+1]);
                }
#pragma unroll
            for (int mt = 0; mt < 2; mt++)
#pragma unroll
                for (int nt = 0; nt < 8; nt++) {
                    int p = nt >> 1, o = (nt & 1) * 2;
                    MMA_BF16(S[mt][nt], qfl[mt], kfh[p][o], kfh[p][o+1]);
                }
        }

#pragma unroll
        for (int mt = 0; mt < 2; mt++) {
            float mx0 = -1e30f, mx1 = -1e30f;
#pragma unroll
            for (int nt = 0; nt < 8; nt++) {
                mx0 = fmaxf(mx0, fmaxf(S[mt][nt][0], S[mt][nt][1]));
                mx1 = fmaxf(mx1, fmaxf(S[mt][nt][2], S[mt][nt][3]));
            }
            mx0 = fmaxf(mx0, __shfl_xor_sync(0xffffffffu, mx0, 1));
            mx0 = fmaxf(mx0, __shfl_xor_sync(0xffffffffu, mx0, 2));
            mx1 = fmaxf(mx1, __shfl_xor_sync(0xffffffffu, mx1, 1));
            mx1 = fmaxf(mx1, __shfl_xor_sync(0xffffffffu, mx1, 2));
            float mn0 = fmaxf(m_run[mt][0], mx0), mn1 = fmaxf(m_run[mt][1], mx1);
            float c0 = __expf(m_run[mt][0] - mn0), c1 = __expf(m_run[mt][1] - mn1);
            m_run[mt][0] = mn0; m_run[mt][1] = mn1;

            float s0 = 0.f, s1 = 0.f;
#pragma unroll
            for (int nt = 0; nt < 8; nt++) {
                S[mt][nt][0] = __expf(S[mt][nt][0] - mn0);
                S[mt][nt][1] = __expf(S[mt][nt][1] - mn0);
                S[mt][nt][2] = __expf(S[mt][nt][2] - mn1);
                S[mt][nt][3] = __expf(S[mt][nt][3] - mn1);
                s0 += S[mt][nt][0] + S[mt][nt][1];
                s1 += S[mt][nt][2] + S[mt][nt][3];
            }
            s0 += __shfl_xor_sync(0xffffffffu, s0, 1);
            s0 += __shfl_xor_sync(0xffffffffu, s0, 2);
            s1 += __shfl_xor_sync(0xffffffffu, s1, 1);
            s1 += __shfl_xor_sync(0xffffffffu, s1, 2);
            l_run[mt][0] = l_run[mt][0] * c0 + s0;
            l_run[mt][1] = l_run[mt][1] * c1 + s1;
#pragma unroll
            for (int d = 0; d < 8; d++) {
                O[mt][d][0] *= c0; O[mt][d][1] *= c0;
                O[mt][d][2] *= c1; O[mt][d][3] *= c1;
            }
        }

#pragma unroll
        for (int ks = 0; ks < 4; ks++) {
            uint32_t pfh[2][4], pfl[2][4];
#pragma unroll
            for (int mt = 0; mt < 2; mt++) {
                bf16_split2(S[mt][2*ks][0],   S[mt][2*ks][1],   pfh[mt][0], pfl[mt][0]);
                bf16_split2(S[mt][2*ks][2],   S[mt][2*ks][3],   pfh[mt][1], pfl[mt][1]);
                bf16_split2(S[mt][2*ks+1][0], S[mt][2*ks+1][1], pfh[mt][2], pfl[mt][2]);
                bf16_split2(S[mt][2*ks+1][2], S[mt][2*ks+1][3], pfh[mt][3], pfl[mt][3]);
            }
            uint32_t vfh[4][4], vfl[4][4];
#pragma unroll
            for (int pd = 0; pd < 4; pd++) {
                uint32_t off = (uint32_t)((ks * 16 + (lane & 15)) * APITCH +
                                          pd * 16 + ((lane >> 4) << 3)) * 2u;
                LDM_X4T(vfh[pd][0], vfh[pd][1], vfh[pd][2], vfh[pd][3], Vs_h + off);
                LDM_X4T(vfl[pd][0], vfl[pd][1], vfl[pd][2], vfl[pd][3], Vs_l + off);
            }
#pragma unroll
            for (int mt = 0; mt < 2; mt++)
#pragma unroll
                for (int dt = 0; dt < 8; dt++) {
                    int pd = dt >> 1, o = (dt & 1) * 2;
                    MMA_BF16(O[mt][dt], pfh[mt], vfh[pd][o], vfh[pd][o+1]);
                }
#pragma unroll
            for (int mt = 0; mt < 2; mt++)
#pragma unroll
                for (int dt = 0; dt < 8; dt++) {
                    int pd = dt >> 1, o = (dt & 1) * 2;
                    MMA_BF16(O[mt][dt], pfh[mt], vfl[pd][o], vfl[pd][o+1]);
                }
#pragma unroll
            for (int mt = 0; mt < 2; mt++)
#pragma unroll
                for (int dt = 0; dt < 8; dt++) {
                    int pd = dt >> 1, o = (dt & 1) * 2;
                    MMA_BF16(O[mt][dt], pfl[mt], vfh[pd][o], vfh[pd][o+1]);
                }
        }

        __syncthreads();
        if (t + 2 < NT) issue(t + 2, t & 1);
    }

    const int g  = lane >> 2;
    const int t2 = (lane & 3) * 2;
    const int b  = bh >> 4;
    const int h  = bh & 15;
#pragma unroll
    for (int mt = 0; mt < 2; mt++) {
        float inv0 = 1.0f / l_run[mt][0], inv1 = 1.0f / l_run[mt][1];
        int row = b * SS + q0 + wm + mt * 16 + g;
#pragma unroll
        for (int dt = 0; dt < 8; dt++) {
            int col = h * HD + dt * 8 + t2;
            uint32_t hi, lo;
            bf16_split2(O[mt][dt][0] * inv0, O[mt][dt][1] * inv0, hi, lo);
            *reinterpret_cast<uint32_t*>(&aoh[(size_t)row * HID + col]) = hi;
            *reinterpret_cast<uint32_t*>(&aol[(size_t)row * HID + col]) = lo;
            bf16_split2(O[mt][dt][2] * inv1, O[mt][dt][3] * inv1, hi, lo);
            *reinterpret_cast<uint32_t*>(&aoh[(size_t)(row + 8) * HID + col]) = hi;
            *reinterpret_cast<uint32_t*>(&aol[(size_t)(row + 8) * HID + col]) = lo;
        }
    }
}

// ----------------------------------------------------------------------------
// Launch
// ----------------------------------------------------------------------------
extern "C" void kernel_launch(void* const* d_in, const int* in_sizes, int n_in,
                              void* d_out, int out_size)
{
    const float* x     = (const float*)d_in[0];
    const float* q_w   = (const float*)d_in[1];
    const float* q_b   = (const float*)d_in[2];
    const float* kv_w  = (const float*)d_in[3];
    const float* kv_b  = (const float*)d_in[4];
    const float* gq    = (const float*)d_in[5];
    const float* gk    = (const float*)d_in[6];
    const float* out_w = (const float*)d_in[7];
    float* out = (float*)d_out;

    __nv_bfloat16 *pqh, *pql, *pkh, *pkl, *pvh, *pvl;
    cudaGetSymbolAddress((void**)&pqh, g_qh);
    cudaGetSymbolAddress((void**)&pql, g_ql);
    cudaGetSymbolAddress((void**)&pkh, g_kh);
    cudaGetSymbolAddress((void**)&pkl, g_kl);
    cudaGetSymbolAddress((void**)&pvh, g_vh);
    cudaGetSymbolAddress((void**)&pvl, g_vl);
    __nv_bfloat16 *pxh, *pxl, *paoh, *paol, *pwh, *pwl, *powh, *powl;
    cudaGetSymbolAddress((void**)&pxh,  g_xh);
    cudaGetSymbolAddress((void**)&pxl,  g_xl);
    cudaGetSymbolAddress((void**)&paoh, g_aoh);
    cudaGetSymbolAddress((void**)&paol, g_aol);
    cudaGetSymbolAddress((void**)&pwh,  g_wh);
    cudaGetSymbolAddress((void**)&pwl,  g_wl);
    cudaGetSymbolAddress((void**)&powh, g_owh);
    cudaGetSymbolAddress((void**)&powl, g_owl);

    cudaFuncSetAttribute(attn_mma,
                         cudaFuncAttributeMaxDynamicSharedMemorySize, ATT_SMEM);

    // Pre-split inputs + all weights (one launch, MLP=4)
    split_all<<<(NSPLIT16 + 255) / 256, 256>>>(x, q_w, kv_w, out_w);

    // Merged QKV projection + fused qknorm/split/relayout (4 warps/CTA)
    {
        dim3 grid((3 * HID) / 128, MR / 128);   // (24, 64)
        gemm_qkv<<<grid, 128>>>(pxh, pxl, pwh, pwl, q_b, kv_b, gq, gk);
    }
    // Attention (tensor cores, 128 queries/CTA, 4 warps x 32 rows, 2 CTA/SM)
    {
        dim3 grid(SS / 128, BB * NH);           // (16, 64)
        attn_mma<<<grid, 128, ATT_SMEM>>>(pqh, pql, pkh, pkl, pvh, pvl, paoh, paol);
    }
    // Output projection (4 warps/CTA)
    {
        dim3 grid(HID / 128, MR / 128);
        gemm_pre<<<grid, 128>>>(paoh, paol, powh, powl, out, MR, HID, HID);
    }
}

// round 16
// speedup vs baseline: 1.1313x; 1.0440x over previous
#include <cuda_runtime.h>
#include <cuda_bf16.h>
#include <math.h>
#include <stdint.h>

// Problem constants
#define BB   4
#define SS   2048
#define HID  1024
#define NH   16
#define HD   64
#define MR   (BB*SS)   // 8192 rows

// Pre-split bf16 operands for attention, layout [b][h][s][64]
__device__ __nv_bfloat16 g_qh[(size_t)MR * HID];
__device__ __nv_bfloat16 g_ql[(size_t)MR * HID];
__device__ __nv_bfloat16 g_kh[(size_t)MR * HID];
__device__ __nv_bfloat16 g_kl[(size_t)MR * HID];
__device__ __nv_bfloat16 g_vh[(size_t)MR * HID];
__device__ __nv_bfloat16 g_vl[(size_t)MR * HID];
// Pre-split GEMM operands
__device__ __nv_bfloat16 g_xh [(size_t)MR * HID];
__device__ __nv_bfloat16 g_xl [(size_t)MR * HID];
__device__ __nv_bfloat16 g_aoh[(size_t)MR * HID];
__device__ __nv_bfloat16 g_aol[(size_t)MR * HID];
__device__ __nv_bfloat16 g_wh [(size_t)3 * HID * HID];   // concat(q_w, kv_w)
__device__ __nv_bfloat16 g_wl [(size_t)3 * HID * HID];
__device__ __nv_bfloat16 g_owh[(size_t)HID * HID];
__device__ __nv_bfloat16 g_owl[(size_t)HID * HID];

__device__ __forceinline__ uint32_t smem_u32(const void* p) {
    uint32_t a;
    asm("{ .reg .u64 t; cvta.to.shared.u64 t, %1; cvt.u32.u64 %0, t; }"
        : "=r"(a) : "l"(p));
    return a;
}

__device__ __forceinline__ void bf16_split2(float x, float y,
                                            uint32_t& hi, uint32_t& lo) {
    __nv_bfloat16 hx = __float2bfloat16(x);
    __nv_bfloat16 hy = __float2bfloat16(y);
    __nv_bfloat16 lx = __float2bfloat16(x - __bfloat162float(hx));
    __nv_bfloat16 ly = __float2bfloat16(y - __bfloat162float(hy));
    __nv_bfloat162 h; h.x = hx; h.y = hy;
    __nv_bfloat162 l; l.x = lx; l.y = ly;
    hi = *reinterpret_cast<uint32_t*>(&h);
    lo = *reinterpret_cast<uint32_t*>(&l);
}

#define LDM_X4(r0, r1, r2, r3, addr) \
    asm volatile("ldmatrix.sync.aligned.m8n8.x4.shared.b16 {%0,%1,%2,%3}, [%4];" \
                 : "=r"(r0), "=r"(r1), "=r"(r2), "=r"(r3) : "r"(addr))
#define LDM_X4T(r0, r1, r2, r3, addr) \
    asm volatile("ldmatrix.sync.aligned.m8n8.x4.trans.shared.b16 {%0,%1,%2,%3}, [%4];" \
                 : "=r"(r0), "=r"(r1), "=r"(r2), "=r"(r3) : "r"(addr))

#define MMA_BF16(d, a, b0v, b1v) \
    asm volatile("mma.sync.aligned.m16n8k16.row.col.f32.bf16.bf16.f32 " \
                 "{%0,%1,%2,%3}, {%4,%5,%6,%7}, {%8,%9}, {%0,%1,%2,%3};" \
                 : "+f"((d)[0]), "+f"((d)[1]), "+f"((d)[2]), "+f"((d)[3]) \
                 : "r"((a)[0]), "r"((a)[1]), "r"((a)[2]), "r"((a)[3]), \
                   "r"(b0v), "r"(b1v))

#define CP_ASYNC16(dst, src) \
    asm volatile("cp.async.cg.shared.global [%0], [%1], 16;" \
                 :: "r"(dst), "l"(src) : "memory")
#define CP_COMMIT() asm volatile("cp.async.commit_group;" ::: "memory")
#define CP_WAIT1()  asm volatile("cp.async.wait_group 1;" ::: "memory")
#define CP_WAIT0()  asm volatile("cp.async.wait_group 0;" ::: "memory")

// ============================================================================
// Merged split: fp32 -> bf16 hi/lo for x, q_w, kv_w, out_w in ONE launch
// (round-10 proven version)
// ============================================================================
#define NX4   (MR * HID / 4)
#define NQW4  (HID * HID / 4)
#define NKVW4 (2 * HID * HID / 4)
#define NOW4  (HID * HID / 4)
#define NSPLIT4 (NX4 + NQW4 + NKVW4 + NOW4)

__global__ __launch_bounds__(256)
void split_all(const float* __restrict__ x, const float* __restrict__ qw,
               const float* __restrict__ kvw, const float* __restrict__ ow)
{
    int i = blockIdx.x * blockDim.x + threadIdx.x;
    if (i >= NSPLIT4) return;
    const float* src;
    __nv_bfloat16 *dh, *dl;
    int off;
    if (i < NX4) {
        src = x; dh = g_xh; dl = g_xl; off = i;
    } else if (i < NX4 + NQW4) {
        src = qw; dh = g_wh; dl = g_wl; off = i - NX4;
    } else if (i < NX4 + NQW4 + NKVW4) {
        src = kvw; off = i - NX4 - NQW4;
        dh = g_wh + (size_t)HID * HID; dl = g_wl + (size_t)HID * HID;
    } else {
        src = ow; dh = g_owh; dl = g_owl; off = i - NX4 - NQW4 - NKVW4;
    }
    float4 v = *reinterpret_cast<const float4*>(src + (size_t)off * 4);
    uint32_t h0, l0, h1, l1;
    bf16_split2(v.x, v.y, h0, l0);
    bf16_split2(v.z, v.w, h1, l1);
    *reinterpret_cast<uint2*>(dh + (size_t)off * 4) = make_uint2(h0, h1);
    *reinterpret_cast<uint2*>(dl + (size_t)off * 4) = make_uint2(l0, l1);
}

// ============================================================================
// Shared GEMM pieces: 4 warps/CTA, warp tile 64m x 64n, CTA tile 128x128,
// 2 CTA/SM (round-10 proven configuration, byte-identical).
// ============================================================================
#define KC    32
#define PITCH 40
#define GT_EL (128 * PITCH)
#define GSTAGE_EL (4 * GT_EL)

#define GEMM_MAINLOOP64(acc)                                                      \
    for (int s = 0; s < NS; s++) {                                                \
        if (s < NS - 1) { CP_WAIT1(); } else { CP_WAIT0(); }                      \
        __syncthreads();                                                          \
        const uint32_t bAh = sb_u + (uint32_t)((s & 1) * GSTAGE_EL) * 2u;         \
        const uint32_t bAl = bAh + (uint32_t)GT_EL * 2u;                          \
        const uint32_t bBh = bAh + (uint32_t)(2 * GT_EL) * 2u;                    \
        const uint32_t bBl = bAh + (uint32_t)(3 * GT_EL) * 2u;                    \
        _Pragma("unroll")                                                         \
        for (int kk = 0; kk < KC; kk += 16) {                                     \
            uint32_t bh[16], bl[16];                                              \
            _Pragma("unroll")                                                     \
            for (int p = 0; p < 4; p++) {                                         \
                uint32_t off = (uint32_t)((wn + p * 16 + b_n) * PITCH + kk + b_k) * 2u; \
                LDM_X4(bh[p*4+0], bh[p*4+1], bh[p*4+2], bh[p*4+3], bBh + off);    \
                LDM_X4(bl[p*4+0], bl[p*4+1], bl[p*4+2], bl[p*4+3], bBl + off);    \
            }                                                                     \
            uint32_t ah[4][4], al[4][4];                                          \
            _Pragma("unroll")                                                     \
            for (int mt = 0; mt < 4; mt++) {                                      \
                uint32_t off = (uint32_t)((wm + mt * 16 + a_row) * PITCH + kk + a_k) * 2u; \
                LDM_X4(ah[mt][0], ah[mt][1], ah[mt][2], ah[mt][3], bAh + off);    \
                LDM_X4(al[mt][0], al[mt][1], al[mt][2], al[mt][3], bAl + off);    \
            }                                                                     \
            _Pragma("unroll")                                                     \
            for (int mt = 0; mt < 4; mt++)                                        \
                _Pragma("unroll")                                                 \
                for (int nt = 0; nt < 8; nt++) {                                  \
                    int p = nt >> 1, o = (nt & 1) * 2;                            \
                    MMA_BF16(acc[mt][nt], ah[mt], bh[p*4+o], bh[p*4+o+1]);        \
                }                                                                 \
            _Pragma("unroll")                                                     \
            for (int mt = 0; mt < 4; mt++)                                        \
                _Pragma("unroll")                                                 \
                for (int nt = 0; nt < 8; nt++) {                                  \
                    int p = nt >> 1, o = (nt & 1) * 2;                            \
                    MMA_BF16(acc[mt][nt], ah[mt], bl[p*4+o], bl[p*4+o+1]);        \
                }                                                                 \
            _Pragma("unroll")                                                     \
            for (int mt = 0; mt < 4; mt++)                                        \
                _Pragma("unroll")                                                 \
                for (int nt = 0; nt < 8; nt++) {                                  \
                    int p = nt >> 1, o = (nt & 1) * 2;                            \
                    MMA_BF16(acc[mt][nt], al[mt], bh[p*4+o], bh[p*4+o+1]);        \
                }                                                                 \
        }                                                                         \
        __syncthreads();                                                          \
        if (s + 2 < NS) issue(s + 2, s & 1);                                      \
    }

#define GEMM_ISSUE_DEF                                                            \
    auto issue = [&](int s, int bsel) {                                           \
        const int k0 = s * KC;                                                    \
        uint32_t base = sb_u + (uint32_t)bsel * GSTAGE_EL * 2u;                   \
        _Pragma("unroll")                                                         \
        for (int a = 0; a < 4; a++) {                                             \
            _Pragma("unroll")                                                     \
            for (int t = 0; t < 4; t++) {                                         \
                int idx = tid + t * 128;                                          \
                int r   = idx >> 2;                                               \
                int c   = (idx & 3) * 8;                                          \
                uint32_t dst = base + (uint32_t)(a * GT_EL + r * PITCH + c) * 2u; \
                CP_ASYNC16(dst, srcs[a] + (size_t)r * K + k0 + c);                \
            }                                                                     \
        }                                                                         \
        CP_COMMIT();                                                              \
    };

// ============================================================================
// Merged QKV GEMM + fused qknorm/split/relayout epilogue (round-10 proven).
// ============================================================================
__global__ __launch_bounds__(128, 2)
void gemm_qkv(const __nv_bfloat16* __restrict__ Ah, const __nv_bfloat16* __restrict__ Al,
              const __nv_bfloat16* __restrict__ Wh, const __nv_bfloat16* __restrict__ Wl,
              const float* __restrict__ q_b, const float* __restrict__ kv_b,
              const float* __restrict__ gq, const float* __restrict__ gk)
{
    __shared__ __align__(16) __nv_bfloat16 sbuf[2 * GSTAGE_EL];

    const int K = HID;
    const int tid  = threadIdx.x;
    const int wid  = tid >> 5;
    const int lane = tid & 31;
    const int row0 = blockIdx.y * 128;
    const int col0 = blockIdx.x * 128;
    const int wm   = (wid >> 1) * 64;
    const int wn   = (wid & 1) * 64;

    const uint32_t sb_u = smem_u32(sbuf);
    const __nv_bfloat16* srcs[4] = {
        Ah + (size_t)row0 * K, Al + (size_t)row0 * K,
        Wh + (size_t)col0 * K, Wl + (size_t)col0 * K };

    const int NS = K / KC;
    GEMM_ISSUE_DEF

    issue(0, 0);
    issue(1, 1);

    const int a_row = lane & 15;
    const int a_k   = (lane >> 4) << 3;
    const int b_n   = (lane & 7) + ((lane >> 4) << 3);
    const int b_k   = lane & 8;

    float acc[4][8][4];
#pragma unroll
    for (int mt = 0; mt < 4; mt++)
#pragma unroll
        for (int nt = 0; nt < 8; nt++)
#pragma unroll
            for (int r = 0; r < 4; r++) acc[mt][nt][r] = 0.f;

    GEMM_MAINLOOP64(acc)

    const int g  = lane >> 2;
    const int t2 = (lane & 3) * 2;

#pragma unroll
    for (int nt = 0; nt < 8; nt++) {
        int col = col0 + wn + nt * 8 + t2;
        float b0 = (col < HID) ? __ldg(&q_b[col])     : __ldg(&kv_b[col - HID]);
        float b1 = (col + 1 < HID) ? __ldg(&q_b[col + 1]) : __ldg(&kv_b[col + 1 - HID]);
#pragma unroll
        for (int mt = 0; mt < 4; mt++) {
            acc[mt][nt][0] += b0; acc[mt][nt][1] += b1;
            acc[mt][nt][2] += b0; acc[mt][nt][3] += b1;
        }
    }

    const int seg = (col0 < HID) ? 0 : (col0 < 2 * HID) ? 1 : 2;
    const int h   = ((col0 & (HID - 1)) + wn) >> 6;
    __nv_bfloat16* dh = (seg == 0) ? g_qh : (seg == 1) ? g_kh : g_vh;
    __nv_bfloat16* dl = (seg == 0) ? g_ql : (seg == 1) ? g_kl : g_vl;
    const float* gamma = (seg == 0) ? gq : gk;

#pragma unroll
    for (int mt = 0; mt < 4; mt++) {
#pragma unroll
        for (int rh = 0; rh < 2; rh++) {
            float inv = 1.0f;
            if (seg < 2) {
                float ssum = 0.f;
#pragma unroll
                for (int nt = 0; nt < 8; nt++) {
                    float v0 = acc[mt][nt][rh * 2 + 0];
                    float v1 = acc[mt][nt][rh * 2 + 1];
                    ssum += v0 * v0 + v1 * v1;
                }
                ssum += __shfl_xor_sync(0xffffffffu, ssum, 1);
                ssum += __shfl_xor_sync(0xffffffffu, ssum, 2);
                inv = 8.0f / fmaxf(sqrtf(ssum), 1e-12f);
            }
            int row  = row0 + wm + mt * 16 + g + rh * 8;
            int b    = row >> 11;
            int srow = row & (SS - 1);
            size_t base = ((size_t)(b * NH + h) * SS + srow) * HD;
#pragma unroll
            for (int nt = 0; nt < 8; nt++) {
                int d = nt * 8 + t2;
                float g0 = 1.f, g1 = 1.f;
                if (seg < 2) {
                    g0 = __ldg(&gamma[h * HD + d]);
                    g1 = __ldg(&gamma[h * HD + d + 1]);
                }
                float v0 = acc[mt][nt][rh * 2 + 0] * inv * g0;
                float v1 = acc[mt][nt][rh * 2 + 1] * inv * g1;
                uint32_t hi, lo;
                bf16_split2(v0, v1, hi, lo);
                *reinterpret_cast<uint32_t*>(&dh[base + d]) = hi;
                *reinterpret_cast<uint32_t*>(&dl[base + d]) = lo;
            }
        }
    }
}

// ============================================================================
// Out-proj GEMM (fp32 out), 4 warps, 64x64 warp tile (round-10 proven).
// ============================================================================
__global__ __launch_bounds__(128, 2)
void gemm_pre(const __nv_bfloat16* __restrict__ Ah, const __nv_bfloat16* __restrict__ Al,
              const __nv_bfloat16* __restrict__ Wh, const __nv_bfloat16* __restrict__ Wl,
              float* __restrict__ C, int M, int N, int K)
{
    __shared__ __align__(16) __nv_bfloat16 sbuf[2 * GSTAGE_EL];

    const int tid  = threadIdx.x;
    const int wid  = tid >> 5;
    const int lane = tid & 31;
    const int row0 = blockIdx.y * 128;
    const int col0 = blockIdx.x * 128;
    const int wm   = (wid >> 1) * 64;
    const int wn   = (wid & 1) * 64;

    const uint32_t sb_u = smem_u32(sbuf);
    const __nv_bfloat16* srcs[4] = {
        Ah + (size_t)row0 * K, Al + (size_t)row0 * K,
        Wh + (size_t)col0 * K, Wl + (size_t)col0 * K };

    const int NS = K / KC;
    GEMM_ISSUE_DEF

    issue(0, 0);
    issue(1, 1);

    const int a_row = lane & 15;
    const int a_k   = (lane >> 4) << 3;
    const int b_n   = (lane & 7) + ((lane >> 4) << 3);
    const int b_k   = lane & 8;

    float acc[4][8][4];
#pragma unroll
    for (int mt = 0; mt < 4; mt++)
#pragma unroll
        for (int nt = 0; nt < 8; nt++)
#pragma unroll
            for (int r = 0; r < 4; r++) acc[mt][nt][r] = 0.f;

    GEMM_MAINLOOP64(acc)

    const int g  = lane >> 2;
    const int t2 = (lane & 3) * 2;
#pragma unroll
    for (int mt = 0; mt < 4; mt++) {
#pragma unroll
        for (int nt = 0; nt < 8; nt++) {
            int row = row0 + wm + mt * 16 + g;
            int col = col0 + wn + nt * 8 + t2;
            *reinterpret_cast<float2*>(&C[(size_t)row * N + col]) =
                make_float2(acc[mt][nt][0], acc[mt][nt][1]);
            *reinterpret_cast<float2*>(&C[(size_t)(row + 8) * N + col]) =
                make_float2(acc[mt][nt][2], acc[mt][nt][3]);
        }
    }
}

// ============================================================================
// Tensor-core flash attention with FIXED softmax max.
// Scores are bounded: |s| <= 64 * max|gamma_q| * max|gamma_k| (qk-norm).
// exp(s - M) with constant M is exact softmax -> no running max, no O
// rescale, no per-tile l reduction. 4 warps x 32 query rows, 2 CTA/SM.
// ============================================================================
#define APITCH 72
#define QTILE_EL  (128 * APITCH)
#define KVARR_EL  (64 * APITCH)
#define BUF_EL    (4 * KVARR_EL)
#define ATT_SMEM  ((2 * QTILE_EL + 2 * BUF_EL) * 2)   // 110592 bytes
#define NT        (SS / 64)

__global__ __launch_bounds__(128, 2)
void attn_mma(const __nv_bfloat16* __restrict__ qh, const __nv_bfloat16* __restrict__ ql,
              const __nv_bfloat16* __restrict__ kh, const __nv_bfloat16* __restrict__ kl,
              const __nv_bfloat16* __restrict__ vh, const __nv_bfloat16* __restrict__ vl,
              const float* __restrict__ gq, const float* __restrict__ gk,
              __nv_bfloat16* __restrict__ aoh, __nv_bfloat16* __restrict__ aol)
{
    extern __shared__ __nv_bfloat16 sm[];
    __nv_bfloat16* Qh = sm;
    __nv_bfloat16* Ql = Qh + QTILE_EL;
    __nv_bfloat16* Bf = Ql + QTILE_EL;

    const int tid  = threadIdx.x;
    const int wid  = tid >> 5;
    const int lane = tid & 31;
    const int bh   = blockIdx.y;
    const int q0   = blockIdx.x * 128;
    const int wm   = wid * 32;
    const int hh   = bh & 15;
    const size_t bh_off = (size_t)bh * SS * HD;

    const __nv_bfloat16* srcs[4] = {kh + bh_off, kl + bh_off, vh + bh_off, vl + bh_off};
    const uint32_t buf_u[2] = { smem_u32(Bf), smem_u32(Bf + BUF_EL) };
    const uint32_t Qh_u = smem_u32(Qh);
    const uint32_t Ql_u = smem_u32(Ql);

    auto issue = [&](int kt, int bsel) {
#pragma unroll
        for (int i = 0; i < 16; i++) {
            const __nv_bfloat16* sp = srcs[i >> 2];
            int rem = ((i & 3) << 7) + tid;
            int r = rem >> 3;
            int c = (rem & 7) * 8;
            uint32_t dst = buf_u[bsel] + (uint32_t)((i >> 2) * KVARR_EL + r * APITCH + c) * 2u;
            CP_ASYNC16(dst, sp + (size_t)(kt * 64 + r) * HD + c);
        }
        CP_COMMIT();
    };

    issue(0, 0);
    issue(1, 1);

    {
        const __nv_bfloat16* qsrc[2] = {qh + bh_off, ql + bh_off};
        __nv_bfloat16* qdst[2] = {Qh, Ql};
#pragma unroll
        for (int i = 0; i < 16; i++) {
            int rem = ((i & 7) << 7) + tid;
            int r = rem >> 3;
            int c = (rem & 7) * 8;
            uint4 v = *reinterpret_cast<const uint4*>(
                qsrc[i >> 3] + (size_t)(q0 + r) * HD + c);
            *reinterpret_cast<uint4*>(qdst[i >> 3] + r * APITCH + c) = v;
        }
    }

    // Fixed softmax max: M = 64 * max|gq[h]| * max|gk[h]| (score upper bound)
    float gm_q = fmaxf(fabsf(__ldg(&gq[hh * HD + lane])),
                       fabsf(__ldg(&gq[hh * HD + lane + 32])));
    float gm_k = fmaxf(fabsf(__ldg(&gk[hh * HD + lane])),
                       fabsf(__ldg(&gk[hh * HD + lane + 32])));
#pragma unroll
    for (int m = 16; m > 0; m >>= 1) {
        gm_q = fmaxf(gm_q, __shfl_xor_sync(0xffffffffu, gm_q, m));
        gm_k = fmaxf(gm_k, __shfl_xor_sync(0xffffffffu, gm_k, m));
    }
    const float Mfix = 64.0f * gm_q * gm_k;

    __syncthreads();

    const int a_row = lane & 15;
    const int a_k   = (lane >> 4) << 3;
    const int b_n   = (lane & 7) + ((lane >> 4) << 3);
    const int b_k   = lane & 8;

    float l_run[2][2];
    float O[2][8][4];
#pragma unroll
    for (int mt = 0; mt < 2; mt++) {
        l_run[mt][0] = 0.f; l_run[mt][1] = 0.f;
#pragma unroll
        for (int d = 0; d < 8; d++)
#pragma unroll
            for (int r = 0; r < 4; r++) O[mt][d][r] = 0.f;
    }

    for (int t = 0; t < NT; t++) {
        if (t < NT - 1) { CP_WAIT1(); } else { CP_WAIT0(); }
        __syncthreads();

        const uint32_t Ks_h = buf_u[t & 1];
        const uint32_t Ks_l = Ks_h + KVARR_EL * 2u;
        const uint32_t Vs_h = Ks_h + 2u * KVARR_EL * 2u;
        const uint32_t Vs_l = Ks_h + 3u * KVARR_EL * 2u;

        float S[2][8][4];
#pragma unroll
        for (int mt = 0; mt < 2; mt++)
#pragma unroll
            for (int nt = 0; nt < 8; nt++)
#pragma unroll
                for (int r = 0; r < 4; r++) S[mt][nt][r] = 0.f;

#pragma unroll
        for (int ks = 0; ks < 4; ks++) {
            uint32_t kfh[4][4], kfl[4][4];
#pragma unroll
            for (int p = 0; p < 4; p++) {
                uint32_t off = (uint32_t)((p * 16 + b_n) * APITCH + ks * 16 + b_k) * 2u;
                LDM_X4(kfh[p][0], kfh[p][1], kfh[p][2], kfh[p][3], Ks_h + off);
                LDM_X4(kfl[p][0], kfl[p][1], kfl[p][2], kfl[p][3], Ks_l + off);
            }
            uint32_t qfh[2][4], qfl[2][4];
#pragma unroll
            for (int mt = 0; mt < 2; mt++) {
                uint32_t off = (uint32_t)((wm + mt * 16 + a_row) * APITCH + ks * 16 + a_k) * 2u;
                LDM_X4(qfh[mt][0], qfh[mt][1], qfh[mt][2], qfh[mt][3], Qh_u + off);
                LDM_X4(qfl[mt][0], qfl[mt][1], qfl[mt][2], qfl[mt][3], Ql_u + off);
            }
#pragma unroll
            for (int mt = 0; mt < 2; mt++)
#pragma unroll
                for (int nt = 0; nt < 8; nt++) {
                    int p = nt >> 1, o = (nt & 1) * 2;
                    MMA_BF16(S[mt][nt], qfh[mt], kfh[p][o], kfh[p][o+1]);
                }
#pragma unroll
            for (int mt = 0; mt < 2; mt++)
#pragma unroll
                for (int nt = 0; nt < 8; nt++) {
                    int p = nt >> 1, o = (nt & 1) * 2;
                    MMA_BF16(S[mt][nt], qfh[mt], kfl[p][o], kfl[p][o+1]);
                }
#pragma unroll
            for (int mt = 0; mt < 2; mt++)
#pragma unroll
                for (int nt = 0; nt < 8; nt++) {
                    int p = nt >> 1, o = (nt & 1) * 2;
                    MMA_BF16(S[mt][nt], qfl[mt], kfh[p][o], kfh[p][o+1]);
                }
        }

        // exp with fixed max; accumulate thread-local l (no shuffles, no rescale)
#pragma unroll
        for (int mt = 0; mt < 2; mt++) {
            float s0 = 0.f, s1 = 0.f;
#pragma unroll
            for (int nt = 0; nt < 8; nt++) {
                S[mt][nt][0] = __expf(S[mt][nt][0] - Mfix);
                S[mt][nt][1] = __expf(S[mt][nt][1] - Mfix);
                S[mt][nt][2] = __expf(S[mt][nt][2] - Mfix);
                S[mt][nt][3] = __expf(S[mt][nt][3] - Mfix);
                s0 += S[mt][nt][0] + S[mt][nt][1];
                s1 += S[mt][nt][2] + S[mt][nt][3];
            }
            l_run[mt][0] += s0;
            l_run[mt][1] += s1;
        }

#pragma unroll
        for (int ks = 0; ks < 4; ks++) {
            uint32_t pfh[2][4], pfl[2][4];
#pragma unroll
            for (int mt = 0; mt < 2; mt++) {
                bf16_split2(S[mt][2*ks][0],   S[mt][2*ks][1],   pfh[mt][0], pfl[mt][0]);
                bf16_split2(S[mt][2*ks][2],   S[mt][2*ks][3],   pfh[mt][1], pfl[mt][1]);
                bf16_split2(S[mt][2*ks+1][0], S[mt][2*ks+1][1], pfh[mt][2], pfl[mt][2]);
                bf16_split2(S[mt][2*ks+1][2], S[mt][2*ks+1][3], pfh[mt][3], pfl[mt][3]);
            }
            uint32_t vfh[4][4], vfl[4][4];
#pragma unroll
            for (int pd = 0; pd < 4; pd++) {
                uint32_t off = (uint32_t)((ks * 16 + (lane & 15)) * APITCH +
                                          pd * 16 + ((lane >> 4) << 3)) * 2u;
                LDM_X4T(vfh[pd][0], vfh[pd][1], vfh[pd][2], vfh[pd][3], Vs_h + off);
                LDM_X4T(vfl[pd][0], vfl[pd][1], vfl[pd][2], vfl[pd][3], Vs_l + off);
            }
#pragma unroll
            for (int mt = 0; mt < 2; mt++)
#pragma unroll
                for (int dt = 0; dt < 8; dt++) {
                    int pd = dt >> 1, o = (dt & 1) * 2;
                    MMA_BF16(O[mt][dt], pfh[mt], vfh[pd][o], vfh[pd][o+1]);
                }
#pragma unroll
            for (int mt = 0; mt < 2; mt++)
#pragma unroll
                for (int dt = 0; dt < 8; dt++) {
                    int pd = dt >> 1, o = (dt & 1) * 2;
                    MMA_BF16(O[mt][dt], pfh[mt], vfl[pd][o], vfl[pd][o+1]);
                }
#pragma unroll
            for (int mt = 0; mt < 2; mt++)
#pragma unroll
                for (int dt = 0; dt < 8; dt++) {
                    int pd = dt >> 1, o = (dt & 1) * 2;
                    MMA_BF16(O[mt][dt], pfl[mt], vfh[pd][o], vfh[pd][o+1]);
                }
        }

        __syncthreads();
        if (t + 2 < NT) issue(t + 2, t & 1);
    }

    // epilogue: reduce l across the quad once, then write bf16 hi/lo of O/l
    const int g  = lane >> 2;
    const int t2 = (lane & 3) * 2;
    const int b  = bh >> 4;
#pragma unroll
    for (int mt = 0; mt < 2; mt++) {
        float l0 = l_run[mt][0], l1 = l_run[mt][1];
        l0 += __shfl_xor_sync(0xffffffffu, l0, 1);
        l0 += __shfl_xor_sync(0xffffffffu, l0, 2);
        l1 += __shfl_xor_sync(0xffffffffu, l1, 1);
        l1 += __shfl_xor_sync(0xffffffffu, l1, 2);
        float inv0 = 1.0f / l0, inv1 = 1.0f / l1;
        int row = b * SS + q0 + wm + mt * 16 + g;
#pragma unroll
        for (int dt = 0; dt < 8; dt++) {
            int col = hh * HD + dt * 8 + t2;
            uint32_t hi, lo;
            bf16_split2(O[mt][dt][0] * inv0, O[mt][dt][1] * inv0, hi, lo);
            *reinterpret_cast<uint32_t*>(&aoh[(size_t)row * HID + col]) = hi;
            *reinterpret_cast<uint32_t*>(&aol[(size_t)row * HID + col]) = lo;
            bf16_split2(O[mt][dt][2] * inv1, O[mt][dt][3] * inv1, hi, lo);
            *reinterpret_cast<uint32_t*>(&aoh[(size_t)(row + 8) * HID + col]) = hi;
            *reinterpret_cast<uint32_t*>(&aol[(size_t)(row + 8) * HID + col]) = lo;
        }
    }
}

// ----------------------------------------------------------------------------
// Launch
// ----------------------------------------------------------------------------
extern "C" void kernel_launch(void* const* d_in, const int* in_sizes, int n_in,
                              void* d_out, int out_size)
{
    const float* x     = (const float*)d_in[0];
    const float* q_w   = (const float*)d_in[1];
    const float* q_b   = (const float*)d_in[2];
    const float* kv_w  = (const float*)d_in[3];
    const float* kv_b  = (const float*)d_in[4];
    const float* gq    = (const float*)d_in[5];
    const float* gk    = (const float*)d_in[6];
    const float* out_w = (const float*)d_in[7];
    float* out = (float*)d_out;

    __nv_bfloat16 *pqh, *pql, *pkh, *pkl, *pvh, *pvl;
    cudaGetSymbolAddress((void**)&pqh, g_qh);
    cudaGetSymbolAddress((void**)&pql, g_ql);
    cudaGetSymbolAddress((void**)&pkh, g_kh);
    cudaGetSymbolAddress((void**)&pkl, g_kl);
    cudaGetSymbolAddress((void**)&pvh, g_vh);
    cudaGetSymbolAddress((void**)&pvl, g_vl);
    __nv_bfloat16 *pxh, *pxl, *paoh, *paol, *pwh, *pwl, *powh, *powl;
    cudaGetSymbolAddress((void**)&pxh,  g_xh);
    cudaGetSymbolAddress((void**)&pxl,  g_xl);
    cudaGetSymbolAddress((void**)&paoh, g_aoh);
    cudaGetSymbolAddress((void**)&paol, g_aol);
    cudaGetSymbolAddress((void**)&pwh,  g_wh);
    cudaGetSymbolAddress((void**)&pwl,  g_wl);
    cudaGetSymbolAddress((void**)&powh, g_owh);
    cudaGetSymbolAddress((void**)&powl, g_owl);

    cudaFuncSetAttribute(attn_mma,
                         cudaFuncAttributeMaxDynamicSharedMemorySize, ATT_SMEM);

    // Pre-split inputs + all weights (one launch)
    split_all<<<(NSPLIT4 + 255) / 256, 256>>>(x, q_w, kv_w, out_w);

    // Merged QKV projection + fused qknorm/split/relayout (4 warps/CTA)
    {
        dim3 grid((3 * HID) / 128, MR / 128);   // (24, 64)
        gemm_qkv<<<grid, 128>>>(pxh, pxl, pwh, pwl, q_b, kv_b, gq, gk);
    }
    // Attention (tensor cores, fixed-max softmax)
    {
        dim3 grid(SS / 128, BB * NH);           // (16, 64)
        attn_mma<<<grid, 128, ATT_SMEM>>>(pqh, pql, pkh, pkl, pvh, pvl,
                                          gq, gk, paoh, paol);
    }
    // Output projection (4 warps/CTA)
    {
        dim3 grid(HID / 128, MR / 128);
        gemm_pre<<<grid, 128>>>(paoh, paol, powh, powl, out, MR, HID, HID);
    }
}